// round 11
// baseline (speedup 1.0000x reference)
#include <cuda_runtime.h>
#include <cuda_fp16.h>
#include <cstdint>

#define B_    64
#define CIN_  96
#define HW_   784
#define HID_  576
#define NE_   4
#define RED_  24
#define RHID_ 24
#define COUT_ 96
#define EPSBN 1e-3f

// ---- scratch (device globals) ----
__device__ float    g_pool[B_ * CIN_];
__device__ float    g_rw  [B_ * NE_];
__device__ float    g_s   [B_ * HID_];
__device__ float    g_zv  [B_ * RED_];
__device__ __align__(16) uint32_t g_xp  [B_ * (CIN_ / 2) * HW_];     // x as f16x2 k-pairs
__device__ __align__(16) uint32_t g_wp  [HID_ * (CIN_ / 2)];         // exp_w f16x2, rows PERMUTED
__device__ __align__(16) uint32_t g_wpwp [B_ * COUT_ * (HID_ / 2)];  // f16x2 pairs along c
__device__ __align__(16) uint32_t g_act1p[B_ * (HID_ / 2) * HW_];    // f16x2 (ch even, ch odd)/pixel
__device__ __align__(16) uint32_t g_act2p[B_ * (HID_ / 2) * HW_];    // f16x2 (ch even, ch odd)/pixel

// sigmoid(v) = 0.5 + 0.5*tanh(v/2): ONE MUFU
__device__ __forceinline__ float sigmoidf_(float v) {
    float t; asm("tanh.approx.f32 %0, %1;" : "=f"(t) : "f"(0.5f * v));
    return fmaf(0.5f, t, 0.5f);
}
// silu(v) = h + h*tanh(h), h = v/2: ONE MUFU
__device__ __forceinline__ float siluf_(float v) {
    float h = 0.5f * v;
    float t; asm("tanh.approx.f32 %0, %1;" : "=f"(t) : "f"(h));
    return fmaf(h, t, h);
}
// half2 silu: ONE MUFU per TWO elements
__device__ __forceinline__ __half2 silu_h2(__half2 y) {
    __half2 h = __hmul2(y, __floats2half2_rn(0.5f, 0.5f));
    uint32_t hv = *(uint32_t*)&h, tv;
    asm("tanh.approx.f16x2 %0, %1;" : "=r"(tv) : "r"(hv));
    return __hfma2(h, *(__half2*)&tv, h);
}

__device__ __forceinline__ uint32_t pack2h(float lo, float hi) {
    uint32_t r; asm("cvt.rn.f16x2.f32 %0, %1, %2;" : "=r"(r) : "f"(hi), "f"(lo)); return r;
}

__device__ __forceinline__ void mma_f16(float* d,
        uint32_t a0, uint32_t a1, uint32_t a2, uint32_t a3,
        uint32_t b0, uint32_t b1) {
    asm volatile(
        "mma.sync.aligned.m16n8k16.row.col.f32.f16.f16.f32 "
        "{%0,%1,%2,%3}, {%4,%5,%6,%7}, {%8,%9}, {%0,%1,%2,%3};\n"
        : "+f"(d[0]), "+f"(d[1]), "+f"(d[2]), "+f"(d[3])
        : "r"(a0), "r"(a1), "r"(a2), "r"(a3), "r"(b0), "r"(b1));
}

// ============================================================
// Kernel 0a: global average pool + pack x into f16x2 k-pairs
// ============================================================
__global__ void k_pool(const float* __restrict__ x) {
    int b = blockIdx.y, t = threadIdx.x, lane = t & 31, w = t >> 5;
    int c0 = blockIdx.x * 16 + w * 2;
    int cp = c0 >> 1;
    const float4* p0 = (const float4*)(x + (size_t)(b * CIN_ + c0) * HW_);
    const float4* p1 = (const float4*)(x + (size_t)(b * CIN_ + c0 + 1) * HW_);
    uint4* op = (uint4*)(g_xp + ((size_t)b * (CIN_ / 2) + cp) * HW_);
    float s0 = 0.f, s1 = 0.f;
    for (int i = lane; i < 196; i += 32) {
        float4 a = p0[i];
        float4 c = p1[i];
        s0 += (a.x + a.y) + (a.z + a.w);
        s1 += (c.x + c.y) + (c.z + c.w);
        op[i] = make_uint4(pack2h(a.x, c.x), pack2h(a.y, c.y),
                           pack2h(a.z, c.z), pack2h(a.w, c.w));
    }
    #pragma unroll
    for (int o = 16; o; o >>= 1) {
        s0 += __shfl_xor_sync(0xffffffffu, s0, o);
        s1 += __shfl_xor_sync(0xffffffffu, s1, o);
    }
    if (!lane) {
        g_pool[b * CIN_ + c0]     = s0 * (1.f / 784.f);
        g_pool[b * CIN_ + c0 + 1] = s1 * (1.f / 784.f);
    }
}

// ============================================================
// Kernel 0c: convert exp_w to f16x2 with PERMUTED rows
// ============================================================
__global__ void k_cvtw(const float* __restrict__ w) {
    int idx = blockIdx.x * 256 + threadIdx.x;
    int m = idx / 48, kp = idx % 48;
    int ch = (m & ~15) + 2 * (m & 7) + ((m >> 3) & 1);
    const float* wr = w + ch * CIN_ + 2 * kp;
    g_wp[idx] = pack2h(wr[0], wr[1]);
}

// ============================================================
// Kernel 0b: routing MLP + softmax  grid=64 block=32
// ============================================================
__global__ void k_rmlp(const float* __restrict__ w1, const float* __restrict__ b1,
                       const float* __restrict__ w2, const float* __restrict__ b2) {
    int b = blockIdx.x, lane = threadIdx.x;
    __shared__ float pool[CIN_];
    __shared__ float hdn[RHID_];
    __shared__ float lg[NE_];
    for (int i = lane; i < CIN_; i += 32) pool[i] = g_pool[b * CIN_ + i];
    __syncwarp();
    if (lane < RHID_) {
        float a = b1[lane];
        for (int c = 0; c < CIN_; c++) a = fmaf(pool[c], w1[lane * CIN_ + c], a);
        hdn[lane] = fmaxf(a, 0.f);
    }
    __syncwarp();
    if (lane < NE_) {
        float a = b2[lane];
        #pragma unroll
        for (int j = 0; j < RHID_; j++) a = fmaf(hdn[j], w2[lane * RHID_ + j], a);
        lg[lane] = a;
    }
    __syncwarp();
    if (lane == 0) {
        float mx = fmaxf(fmaxf(lg[0], lg[1]), fmaxf(lg[2], lg[3]));
        float e[4], s = 0.f;
        #pragma unroll
        for (int i = 0; i < 4; i++) { e[i] = __expf(lg[i] - mx); s += e[i]; }
        float inv = 1.f / s;
        #pragma unroll
        for (int i = 0; i < 4; i++) g_rw[b * NE_ + i] = e[i] * inv;
    }
}

// ============================================================
// Kernel 1: expand 1x1 GEMM (f16 mma) + BN1 + SiLU(f16x2 tanh) -> act1p
// grid=(9,64) block=256 — block = (o-tile, batch), loops 7 hw-subtiles
// ============================================================
__global__ void k_expand(const float* __restrict__ gg, const float* __restrict__ bb,
                         const float* __restrict__ mm, const float* __restrict__ vv) {
    __shared__ uint32_t ws[64][52];
    __shared__ uint32_t xs[48][120];
    int b = blockIdx.y, o0 = blockIdx.x * 64;
    int t = threadIdx.x, lane = t & 31, wid = t >> 5;
    int gid = lane >> 2, tig = lane & 3;
    int wm = wid >> 1, wn = wid & 1;

    for (int i = t; i < 768; i += 256) {
        int m = i / 12, q = i % 12;
        *(uint4*)&ws[m][4 * q] = *(const uint4*)(g_wp + (o0 + m) * 48 + 4 * q);
    }
    __syncthreads();

    int m = wm * 16 + gid;
    uint32_t A[6][4];
    #pragma unroll
    for (int s = 0; s < 6; s++) {
        int kp = s * 8 + tig;
        A[s][0] = ws[m][kp];     A[s][1] = ws[m + 8][kp];
        A[s][2] = ws[m][kp + 4]; A[s][3] = ws[m + 8][kp + 4];
    }

    int ch0 = o0 + wm * 16 + 2 * gid;
    int ch1 = ch0 + 1;
    float inv0 = gg[ch0] * rsqrtf(vv[ch0] + EPSBN), base0 = bb[ch0] - mm[ch0] * inv0;
    float inv1 = gg[ch1] * rsqrtf(vv[ch1] + EPSBN), base1 = bb[ch1] - mm[ch1] * inv1;
    uint32_t* op = g_act1p + ((size_t)b * (HID_ / 2) + (ch0 >> 1)) * HW_;
    const uint32_t* xpb0 = g_xp + (size_t)b * (CIN_ / 2) * HW_;

    int kp0 = t / 28, q0 = t % 28;

    for (int hwt = 0; hwt < 7; hwt++) {
        int hw0 = hwt * 112;
        __syncthreads();
        {
            const uint32_t* xpb = xpb0 + hw0;
            int kp = kp0, q = q0;
            #pragma unroll
            for (int it = 0; it < 6; it++) {
                if (t + it * 256 < 1344)
                    *(uint4*)&xs[kp][4 * q] = *(const uint4*)(xpb + kp * HW_ + 4 * q);
                q += 4; kp += 9;
                if (q >= 28) { q -= 28; kp++; }
            }
        }
        __syncthreads();

        float acc[7][4] = {};
        #pragma unroll
        for (int s = 0; s < 6; s++) {
            int kp = s * 8 + tig;
            #pragma unroll
            for (int ni = 0; ni < 7; ni++) {
                int n = wn * 56 + ni * 8 + gid;
                mma_f16(acc[ni], A[s][0], A[s][1], A[s][2], A[s][3],
                        xs[kp][n], xs[kp + 4][n]);
            }
        }

        #pragma unroll
        for (int ni = 0; ni < 7; ni++) {
            int n = hw0 + wn * 56 + ni * 8 + tig * 2;
            float y0 = fmaf(acc[ni][0], inv0, base0);
            float y1 = fmaf(acc[ni][1], inv0, base0);
            float y2 = fmaf(acc[ni][2], inv1, base1);
            float y3 = fmaf(acc[ni][3], inv1, base1);
            uint32_t p02 = pack2h(y0, y2), p13 = pack2h(y1, y3);
            __half2 a02 = silu_h2(*(__half2*)&p02);
            __half2 a13 = silu_h2(*(__half2*)&p13);
            *(uint2*)(op + n) = make_uint2(*(uint32_t*)&a02, *(uint32_t*)&a13);
        }
    }
}

// ============================================================
// Kernel 2: MoE depthwise 5x5 HFMA2 + BN2(h2) + SiLU(f16x2 tanh) + SE pool
// grid=(36,64) block=224
// ============================================================
#define TSTRIDE 1064
__global__ void __launch_bounds__(224, 4) k_dw(
                     const float* __restrict__ dw,
                     const float* __restrict__ gg, const float* __restrict__ bb,
                     const float* __restrict__ mm, const float* __restrict__ vv) {
    int b = blockIdx.y, t = threadIdx.x;
    int cp0 = blockIdx.x * 8;
    __shared__ __half2 tile[8 * TSTRIDE];
    __shared__ __half2 kern[8][25];
    __shared__ float rwv[NE_];
    __shared__ float2 part[8][28];

    if (t < NE_) rwv[t] = g_rw[b * NE_ + t];
    const uint32_t* in = g_act1p + ((size_t)b * (HID_ / 2) + cp0) * HW_;
    for (int idx = t; idx < 8192; idx += 224) {
        int i = idx >> 10, p = idx & 1023;
        int r = p >> 5, c = p & 31;
        int rr = r - 2, cc = c - 2;
        bool ok = (rr >= 0 && rr < 28 && cc >= 0 && cc < 28);
        uint32_t wv = ok ? in[(size_t)i * HW_ + rr * 28 + cc] : 0u;
        *(uint32_t*)&tile[i * TSTRIDE + r * 33 + c] = wv;
    }
    __syncthreads();
    if (t < 200) {
        int pl = t / 25, kk = t % 25;
        int ch = 2 * (cp0 + pl);
        float s0 = 0.f, s1 = 0.f;
        #pragma unroll
        for (int e = 0; e < NE_; e++) {
            s0 = fmaf(rwv[e], dw[(e * HID_ + ch)     * 25 + kk], s0);
            s1 = fmaf(rwv[e], dw[(e * HID_ + ch + 1) * 25 + kk], s1);
        }
        kern[pl][kk] = __floats2half2_rn(s0, s1);
    }
    __syncthreads();

    int pl = t / 28;
    int patch = t % 28;
    int rg = patch / 7, cg = patch % 7;
    int r0 = rg * 7, cb = cg * 4;
    const __half2* tp = tile + pl * TSTRIDE;

    __half2 kr[25];
    #pragma unroll
    for (int i = 0; i < 25; i++) kr[i] = kern[pl][i];

    __half2 acc[7][4];
    #pragma unroll
    for (int j = 0; j < 7; j++)
        #pragma unroll
        for (int c2 = 0; c2 < 4; c2++) acc[j][c2] = __floats2half2_rn(0.f, 0.f);

    #pragma unroll
    for (int u = 0; u < 11; u++) {
        __half2 w8[8];
        #pragma unroll
        for (int wj = 0; wj < 8; wj++) w8[wj] = tp[(r0 + u) * 33 + cb + wj];
        #pragma unroll
        for (int j = 0; j < 7; j++) {
            if (u >= j && u <= j + 4) {
                int k = u - j;
                #pragma unroll
                for (int c2 = 0; c2 < 4; c2++)
                    #pragma unroll
                    for (int w2 = 0; w2 < 5; w2++)
                        acc[j][c2] = __hfma2(w8[c2 + w2], kr[k * 5 + w2], acc[j][c2]);
            }
        }
    }

    int ch0 = 2 * (cp0 + pl), ch1 = ch0 + 1;
    float inv0 = gg[ch0] * rsqrtf(vv[ch0] + EPSBN), base0 = bb[ch0] - mm[ch0] * inv0;
    float inv1 = gg[ch1] * rsqrtf(vv[ch1] + EPSBN), base1 = bb[ch1] - mm[ch1] * inv1;
    __half2 inv2  = __floats2half2_rn(inv0, inv1);
    __half2 base2 = __floats2half2_rn(base0, base1);
    float ls0 = 0.f, ls1 = 0.f;
    uint32_t* op = g_act2p + ((size_t)b * (HID_ / 2) + cp0 + pl) * HW_;
    #pragma unroll
    for (int j = 0; j < 7; j++) {
        uint32_t pk[4];
        #pragma unroll
        for (int c2 = 0; c2 < 4; c2++) {
            __half2 y = __hfma2(acc[j][c2], inv2, base2);
            __half2 a = silu_h2(y);
            float2 f = __half22float2(a);
            ls0 += f.x; ls1 += f.y;
            pk[c2] = *(uint32_t*)&a;
        }
        *(uint4*)(op + (r0 + j) * 28 + cb) = make_uint4(pk[0], pk[1], pk[2], pk[3]);
    }
    part[pl][patch] = make_float2(ls0, ls1);
    __syncthreads();
    if (t < 16) {
        int p2 = t >> 1, hi = t & 1;
        float s = 0.f;
        #pragma unroll
        for (int i = 0; i < 28; i++) s += hi ? part[p2][i].y : part[p2][i].x;
        g_s[b * HID_ + 2 * (cp0 + p2) + hi] = s * (1.f / 784.f);
    }
}

// ============================================================
// Kernel 3: SE first layer -> g_zv   grid=64 block=256
// ============================================================
__global__ void k_sez(const float* __restrict__ w1, const float* __restrict__ b1) {
    int b = blockIdx.x, t = threadIdx.x, lane = t & 31, w = t >> 5;
    __shared__ float sv[HID_];
    for (int i = t; i < HID_; i += 256) sv[i] = g_s[b * HID_ + i];
    __syncthreads();
    #pragma unroll
    for (int i = 0; i < 3; i++) {
        int r = w + 8 * i;
        float s = 0.f;
        for (int c = lane; c < HID_; c += 32) s = fmaf(sv[c], w1[r * HID_ + c], s);
        #pragma unroll
        for (int o = 16; o; o >>= 1) s += __shfl_xor_sync(0xffffffffu, s, o);
        if (!lane) g_zv[b * RED_ + r] = siluf_(s + b1[r]);
    }
}

// ============================================================
// Kernel 4: SE second layer + mix pointwise weights + fold scale (f16x2)
// ============================================================
__global__ void k_wpw(const float* __restrict__ pw,
                      const float* __restrict__ w2, const float* __restrict__ b2) {
    int t = threadIdx.x, lane = t & 31, ty = t >> 5;
    int o = blockIdx.y * 8 + ty;
    int cp = blockIdx.x * 32 + lane;
    __shared__ float rws[B_][NE_];
    __shared__ float zvs[B_][RED_];
    __shared__ float scs[B_][64];

    for (int i = t; i < B_ * NE_; i += 256) rws[i >> 2][i & 3] = g_rw[i];
    for (int i = t; i < B_ * RED_; i += 256) zvs[i / RED_][i % RED_] = g_zv[i];
    __syncthreads();
    for (int idx = t; idx < B_ * 64; idx += 256) {
        int bb2 = idx >> 6, j = idx & 63;
        int c = blockIdx.x * 64 + j;
        float a = b2[c];
        #pragma unroll
        for (int r = 0; r < RED_; r++) a = fmaf(zvs[bb2][r], w2[c * RED_ + r], a);
        scs[bb2][j] = sigmoidf_(a);
    }
    __syncthreads();

    float p0[NE_], p1[NE_];
    #pragma unroll
    for (int e = 0; e < NE_; e++) {
        float2 v = *(const float2*)(pw + (size_t)(e * COUT_ + o) * HID_ + 2 * cp);
        p0[e] = v.x; p1[e] = v.y;
    }
    int jl = lane * 2;
    for (int b = 0; b < B_; b++) {
        float w0 = 0.f, w1v = 0.f;
        #pragma unroll
        for (int e = 0; e < NE_; e++) {
            w0  = fmaf(rws[b][e], p0[e], w0);
            w1v = fmaf(rws[b][e], p1[e], w1v);
        }
        g_wpwp[(size_t)(b * COUT_ + o) * (HID_ / 2) + cp] =
            pack2h(w0 * scs[b][jl], w1v * scs[b][jl + 1]);
    }
}

// ============================================================
// Kernel 5: pointwise GEMM (f16 mma) + BN3 + residual
// grid=(9,64) block=256  BM=96 BN=96 BK=64
// ============================================================
__global__ void k_pw(const float* __restrict__ x,
                     const float* __restrict__ gg, const float* __restrict__ bb,
                     const float* __restrict__ mm, const float* __restrict__ vv,
                     float* __restrict__ out) {
    __shared__ uint32_t ws[96][36];
    __shared__ uint32_t xs[32][104];
    int b = blockIdx.y, n0 = blockIdx.x * 96;
    int t = threadIdx.x, lane = t & 31, wid = t >> 5;
    int gid = lane >> 2, tig = lane & 3;
    int wm = wid >> 2, wn = wid & 3;

    float acc[3][3][4] = {};
    const uint32_t* wp = g_wpwp + (size_t)b * COUT_ * (HID_ / 2);
    const uint32_t* ap = g_act2p + (size_t)b * (HID_ / 2) * HW_;

    for (int k0p = 0; k0p < HID_ / 2; k0p += 32) {
        for (int i = t; i < 3072; i += 256) {
            int m = i >> 5, kp = i & 31;
            ws[m][kp] = wp[m * (HID_ / 2) + k0p + kp];
        }
        for (int i = t; i < 3072; i += 256) {
            int kp = i / 96, n = i % 96;
            int col = n0 + n;
            xs[kp][n] = (col < HW_) ? ap[(k0p + kp) * HW_ + col] : 0u;
        }
        __syncthreads();
        #pragma unroll
        for (int s = 0; s < 4; s++) {
            int kp = s * 8 + tig;
            uint32_t A[3][4];
            #pragma unroll
            for (int mi = 0; mi < 3; mi++) {
                int m = wm * 48 + mi * 16 + gid;
                A[mi][0] = ws[m][kp];     A[mi][1] = ws[m + 8][kp];
                A[mi][2] = ws[m][kp + 4]; A[mi][3] = ws[m + 8][kp + 4];
            }
            #pragma unroll
            for (int ni = 0; ni < 3; ni++) {
                int n = wn * 24 + ni * 8 + gid;
                uint32_t b0 = xs[kp][n], b1 = xs[kp + 4][n];
                #pragma unroll
                for (int mi = 0; mi < 3; mi++)
                    mma_f16(acc[mi][ni], A[mi][0], A[mi][1], A[mi][2], A[mi][3], b0, b1);
            }
        }
        __syncthreads();
    }

    #pragma unroll
    for (int mi = 0; mi < 3; mi++) {
        int oA = wm * 48 + mi * 16 + gid;
        int oB = oA + 8;
        float invA = gg[oA] * rsqrtf(vv[oA] + EPSBN), baseA = bb[oA] - mm[oA] * invA;
        float invB = gg[oB] * rsqrtf(vv[oB] + EPSBN), baseB = bb[oB] - mm[oB] * invB;
        #pragma unroll
        for (int ni = 0; ni < 3; ni++) {
            int col = n0 + wn * 24 + ni * 8 + tig * 2;
            if (col < HW_) {
                size_t iA = (size_t)(b * COUT_ + oA) * HW_ + col;
                size_t iB = (size_t)(b * COUT_ + oB) * HW_ + col;
                float2 rA = *(const float2*)(x + iA);
                float2 rB = *(const float2*)(x + iB);
                *(float2*)(out + iA) = make_float2(fmaf(acc[mi][ni][0], invA, baseA) + rA.x,
                                                   fmaf(acc[mi][ni][1], invA, baseA) + rA.y);
                *(float2*)(out + iB) = make_float2(fmaf(acc[mi][ni][2], invB, baseB) + rB.x,
                                                   fmaf(acc[mi][ni][3], invB, baseB) + rB.y);
            }
        }
    }
}

// ============================================================
extern "C" void kernel_launch(void* const* d_in, const int* in_sizes, int n_in,
                              void* d_out, int out_size) {
    const float* x     = (const float*)d_in[0];
    const float* r_w1  = (const float*)d_in[1];
    const float* r_b1  = (const float*)d_in[2];
    const float* r_w2  = (const float*)d_in[3];
    const float* r_b2  = (const float*)d_in[4];
    const float* exp_w = (const float*)d_in[5];
    const float* bn1_g = (const float*)d_in[6];
    const float* bn1_b = (const float*)d_in[7];
    const float* bn1_m = (const float*)d_in[8];
    const float* bn1_v = (const float*)d_in[9];
    const float* dw_w  = (const float*)d_in[10];
    const float* bn2_g = (const float*)d_in[11];
    const float* bn2_b = (const float*)d_in[12];
    const float* bn2_m = (const float*)d_in[13];
    const float* bn2_v = (const float*)d_in[14];
    const float* se_w1 = (const float*)d_in[15];
    const float* se_b1 = (const float*)d_in[16];
    const float* se_w2 = (const float*)d_in[17];
    const float* se_b2 = (const float*)d_in[18];
    const float* pw_w  = (const float*)d_in[19];
    const float* bn3_g = (const float*)d_in[20];
    const float* bn3_b = (const float*)d_in[21];
    const float* bn3_m = (const float*)d_in[22];
    const float* bn3_v = (const float*)d_in[23];
    float* out = (float*)d_out;

    k_pool  <<<dim3(6, B_), 256>>>(x);
    k_cvtw  <<<108, 256>>>(exp_w);
    k_rmlp  <<<B_, 32>>>(r_w1, r_b1, r_w2, r_b2);
    k_expand<<<dim3(9, B_), 256>>>(bn1_g, bn1_b, bn1_m, bn1_v);
    k_dw    <<<dim3(36, B_), 224>>>(dw_w, bn2_g, bn2_b, bn2_m, bn2_v);
    k_sez   <<<B_, 256>>>(se_w1, se_b1);
    k_wpw   <<<dim3(9, 12), 256>>>(pw_w, se_w2, se_b2);
    k_pw    <<<dim3(9, B_), 256>>>(x, bn3_g, bn3_b, bn3_m, bn3_v, out);
}

// round 12
// speedup vs baseline: 1.5546x; 1.5546x over previous
#include <cuda_runtime.h>
#include <cuda_fp16.h>
#include <cstdint>

#define B_    64
#define CIN_  96
#define HW_   784
#define HID_  576
#define NE_   4
#define RED_  24
#define RHID_ 24
#define COUT_ 96
#define EPSBN 1e-3f

// ---- scratch (device globals) ----
__device__ float    g_pool[B_ * CIN_];
__device__ float    g_rw  [B_ * NE_];
__device__ float    g_s   [B_ * HID_];
__device__ float    g_zv  [B_ * RED_];
__device__ __align__(16) uint32_t g_xp  [B_ * (CIN_ / 2) * HW_];     // x as f16x2 k-pairs
__device__ __align__(16) uint32_t g_wp  [HID_ * (CIN_ / 2)];         // exp_w f16x2, rows PERMUTED
__device__ __align__(16) uint32_t g_wpwp [B_ * COUT_ * (HID_ / 2)];  // f16x2 pairs along c
__device__ __align__(16) uint32_t g_act1p[B_ * (HID_ / 2) * HW_];    // f16x2 (ch even, ch odd)/pixel
__device__ __align__(16) uint32_t g_act2p[B_ * (HID_ / 2) * HW_];    // f16x2 (ch even, ch odd)/pixel

// silu(v) = h + h*tanh(h), h = v/2 — ONE scalar MUFU
__device__ __forceinline__ float siluf_(float v) {
    float h = 0.5f * v;
    float t; asm("tanh.approx.f32 %0, %1;" : "=f"(t) : "f"(h));
    return fmaf(h, t, h);
}
// sigmoid(v) = 0.5 + 0.5*tanh(v/2) — ONE scalar MUFU
__device__ __forceinline__ float sigmoidf_(float v) {
    float t; asm("tanh.approx.f32 %0, %1;" : "=f"(t) : "f"(0.5f * v));
    return fmaf(0.5f, t, 0.5f);
}

__device__ __forceinline__ uint32_t pack2h(float lo, float hi) {
    uint32_t r; asm("cvt.rn.f16x2.f32 %0, %1, %2;" : "=r"(r) : "f"(hi), "f"(lo)); return r;
}

__device__ __forceinline__ void mma_f16(float* d,
        uint32_t a0, uint32_t a1, uint32_t a2, uint32_t a3,
        uint32_t b0, uint32_t b1) {
    asm volatile(
        "mma.sync.aligned.m16n8k16.row.col.f32.f16.f16.f32 "
        "{%0,%1,%2,%3}, {%4,%5,%6,%7}, {%8,%9}, {%0,%1,%2,%3};\n"
        : "+f"(d[0]), "+f"(d[1]), "+f"(d[2]), "+f"(d[3])
        : "r"(a0), "r"(a1), "r"(a2), "r"(a3), "r"(b0), "r"(b1));
}

// ============================================================
// Kernel 0a: global average pool + pack x into f16x2 k-pairs
// ============================================================
__global__ void k_pool(const float* __restrict__ x) {
    int b = blockIdx.y, t = threadIdx.x, lane = t & 31, w = t >> 5;
    int c0 = blockIdx.x * 16 + w * 2;
    int cp = c0 >> 1;
    const float4* p0 = (const float4*)(x + (size_t)(b * CIN_ + c0) * HW_);
    const float4* p1 = (const float4*)(x + (size_t)(b * CIN_ + c0 + 1) * HW_);
    uint4* op = (uint4*)(g_xp + ((size_t)b * (CIN_ / 2) + cp) * HW_);
    float s0 = 0.f, s1 = 0.f;
    for (int i = lane; i < 196; i += 32) {
        float4 a = p0[i];
        float4 c = p1[i];
        s0 += (a.x + a.y) + (a.z + a.w);
        s1 += (c.x + c.y) + (c.z + c.w);
        op[i] = make_uint4(pack2h(a.x, c.x), pack2h(a.y, c.y),
                           pack2h(a.z, c.z), pack2h(a.w, c.w));
    }
    #pragma unroll
    for (int o = 16; o; o >>= 1) {
        s0 += __shfl_xor_sync(0xffffffffu, s0, o);
        s1 += __shfl_xor_sync(0xffffffffu, s1, o);
    }
    if (!lane) {
        g_pool[b * CIN_ + c0]     = s0 * (1.f / 784.f);
        g_pool[b * CIN_ + c0 + 1] = s1 * (1.f / 784.f);
    }
}

// ============================================================
// Kernel 0c: convert exp_w to f16x2 with PERMUTED rows
// ============================================================
__global__ void k_cvtw(const float* __restrict__ w) {
    int idx = blockIdx.x * 256 + threadIdx.x;
    int m = idx / 48, kp = idx % 48;
    int ch = (m & ~15) + 2 * (m & 7) + ((m >> 3) & 1);
    const float* wr = w + ch * CIN_ + 2 * kp;
    g_wp[idx] = pack2h(wr[0], wr[1]);
}

// ============================================================
// Kernel 0b: routing MLP + softmax  grid=64 block=32
// ============================================================
__global__ void k_rmlp(const float* __restrict__ w1, const float* __restrict__ b1,
                       const float* __restrict__ w2, const float* __restrict__ b2) {
    int b = blockIdx.x, lane = threadIdx.x;
    __shared__ float pool[CIN_];
    __shared__ float hdn[RHID_];
    __shared__ float lg[NE_];
    for (int i = lane; i < CIN_; i += 32) pool[i] = g_pool[b * CIN_ + i];
    __syncwarp();
    if (lane < RHID_) {
        float a = b1[lane];
        for (int c = 0; c < CIN_; c++) a = fmaf(pool[c], w1[lane * CIN_ + c], a);
        hdn[lane] = fmaxf(a, 0.f);
    }
    __syncwarp();
    if (lane < NE_) {
        float a = b2[lane];
        #pragma unroll
        for (int j = 0; j < RHID_; j++) a = fmaf(hdn[j], w2[lane * RHID_ + j], a);
        lg[lane] = a;
    }
    __syncwarp();
    if (lane == 0) {
        float mx = fmaxf(fmaxf(lg[0], lg[1]), fmaxf(lg[2], lg[3]));
        float e[4], s = 0.f;
        #pragma unroll
        for (int i = 0; i < 4; i++) { e[i] = __expf(lg[i] - mx); s += e[i]; }
        float inv = 1.f / s;
        #pragma unroll
        for (int i = 0; i < 4; i++) g_rw[b * NE_ + i] = e[i] * inv;
    }
}

// ============================================================
// Kernel 1: expand 1x1 GEMM (f16 mma) + BN1 + SiLU -> act1p
// grid=(9,64) block=256 — block = (o-tile, batch), loops 7 hw-subtiles
// ============================================================
__global__ void k_expand(const float* __restrict__ gg, const float* __restrict__ bb,
                         const float* __restrict__ mm, const float* __restrict__ vv) {
    __shared__ uint32_t ws[64][52];
    __shared__ uint32_t xs[48][120];
    int b = blockIdx.y, o0 = blockIdx.x * 64;
    int t = threadIdx.x, lane = t & 31, wid = t >> 5;
    int gid = lane >> 2, tig = lane & 3;
    int wm = wid >> 1, wn = wid & 1;

    for (int i = t; i < 768; i += 256) {
        int m = i / 12, q = i % 12;
        *(uint4*)&ws[m][4 * q] = *(const uint4*)(g_wp + (o0 + m) * 48 + 4 * q);
    }
    __syncthreads();

    int m = wm * 16 + gid;
    uint32_t A[6][4];
    #pragma unroll
    for (int s = 0; s < 6; s++) {
        int kp = s * 8 + tig;
        A[s][0] = ws[m][kp];     A[s][1] = ws[m + 8][kp];
        A[s][2] = ws[m][kp + 4]; A[s][3] = ws[m + 8][kp + 4];
    }

    int ch0 = o0 + wm * 16 + 2 * gid;
    int ch1 = ch0 + 1;
    float inv0 = gg[ch0] * rsqrtf(vv[ch0] + EPSBN), base0 = bb[ch0] - mm[ch0] * inv0;
    float inv1 = gg[ch1] * rsqrtf(vv[ch1] + EPSBN), base1 = bb[ch1] - mm[ch1] * inv1;
    uint32_t* op = g_act1p + ((size_t)b * (HID_ / 2) + (ch0 >> 1)) * HW_;
    const uint32_t* xpb0 = g_xp + (size_t)b * (CIN_ / 2) * HW_;

    int kp0 = t / 28, q0 = t % 28;

    for (int hwt = 0; hwt < 7; hwt++) {
        int hw0 = hwt * 112;
        __syncthreads();
        {
            const uint32_t* xpb = xpb0 + hw0;
            int kp = kp0, q = q0;
            #pragma unroll
            for (int it = 0; it < 6; it++) {
                if (t + it * 256 < 1344)
                    *(uint4*)&xs[kp][4 * q] = *(const uint4*)(xpb + kp * HW_ + 4 * q);
                q += 4; kp += 9;
                if (q >= 28) { q -= 28; kp++; }
            }
        }
        __syncthreads();

        float acc[7][4] = {};
        #pragma unroll
        for (int s = 0; s < 6; s++) {
            int kp = s * 8 + tig;
            #pragma unroll
            for (int ni = 0; ni < 7; ni++) {
                int n = wn * 56 + ni * 8 + gid;
                mma_f16(acc[ni], A[s][0], A[s][1], A[s][2], A[s][3],
                        xs[kp][n], xs[kp + 4][n]);
            }
        }

        #pragma unroll
        for (int ni = 0; ni < 7; ni++) {
            int n = hw0 + wn * 56 + ni * 8 + tig * 2;
            float a0v = siluf_(fmaf(acc[ni][0], inv0, base0));
            float a1v = siluf_(fmaf(acc[ni][1], inv0, base0));
            float a2v = siluf_(fmaf(acc[ni][2], inv1, base1));
            float a3v = siluf_(fmaf(acc[ni][3], inv1, base1));
            *(uint2*)(op + n) = make_uint2(pack2h(a0v, a2v), pack2h(a1v, a3v));
        }
    }
}

// ============================================================
// Kernel 2: MoE depthwise 5x5 HFMA2 + BN2 + SiLU + SE pool
// grid=(36,64) block=224
// ============================================================
#define TSTRIDE 1064
__global__ void __launch_bounds__(224, 4) k_dw(
                     const float* __restrict__ dw,
                     const float* __restrict__ gg, const float* __restrict__ bb,
                     const float* __restrict__ mm, const float* __restrict__ vv) {
    int b = blockIdx.y, t = threadIdx.x;
    int cp0 = blockIdx.x * 8;
    __shared__ __half2 tile[8 * TSTRIDE];
    __shared__ __half2 kern[8][25];
    __shared__ float rwv[NE_];
    __shared__ float2 part[8][28];

    if (t < NE_) rwv[t] = g_rw[b * NE_ + t];
    const uint32_t* in = g_act1p + ((size_t)b * (HID_ / 2) + cp0) * HW_;
    for (int idx = t; idx < 8192; idx += 224) {
        int i = idx >> 10, p = idx & 1023;
        int r = p >> 5, c = p & 31;
        int rr = r - 2, cc = c - 2;
        bool ok = (rr >= 0 && rr < 28 && cc >= 0 && cc < 28);
        uint32_t wv = ok ? in[(size_t)i * HW_ + rr * 28 + cc] : 0u;
        *(uint32_t*)&tile[i * TSTRIDE + r * 33 + c] = wv;
    }
    __syncthreads();
    if (t < 200) {
        int pl = t / 25, kk = t % 25;
        int ch = 2 * (cp0 + pl);
        float s0 = 0.f, s1 = 0.f;
        #pragma unroll
        for (int e = 0; e < NE_; e++) {
            s0 = fmaf(rwv[e], dw[(e * HID_ + ch)     * 25 + kk], s0);
            s1 = fmaf(rwv[e], dw[(e * HID_ + ch + 1) * 25 + kk], s1);
        }
        kern[pl][kk] = __floats2half2_rn(s0, s1);
    }
    __syncthreads();

    int pl = t / 28;
    int patch = t % 28;
    int rg = patch / 7, cg = patch % 7;
    int r0 = rg * 7, cb = cg * 4;
    const __half2* tp = tile + pl * TSTRIDE;

    __half2 kr[25];
    #pragma unroll
    for (int i = 0; i < 25; i++) kr[i] = kern[pl][i];

    __half2 acc[7][4];
    #pragma unroll
    for (int j = 0; j < 7; j++)
        #pragma unroll
        for (int c2 = 0; c2 < 4; c2++) acc[j][c2] = __floats2half2_rn(0.f, 0.f);

    #pragma unroll
    for (int u = 0; u < 11; u++) {
        __half2 w8[8];
        #pragma unroll
        for (int wj = 0; wj < 8; wj++) w8[wj] = tp[(r0 + u) * 33 + cb + wj];
        #pragma unroll
        for (int j = 0; j < 7; j++) {
            if (u >= j && u <= j + 4) {
                int k = u - j;
                #pragma unroll
                for (int c2 = 0; c2 < 4; c2++)
                    #pragma unroll
                    for (int w2 = 0; w2 < 5; w2++)
                        acc[j][c2] = __hfma2(w8[c2 + w2], kr[k * 5 + w2], acc[j][c2]);
            }
        }
    }

    int ch0 = 2 * (cp0 + pl), ch1 = ch0 + 1;
    float inv0 = gg[ch0] * rsqrtf(vv[ch0] + EPSBN), base0 = bb[ch0] - mm[ch0] * inv0;
    float inv1 = gg[ch1] * rsqrtf(vv[ch1] + EPSBN), base1 = bb[ch1] - mm[ch1] * inv1;
    float ls0 = 0.f, ls1 = 0.f;
    uint32_t* op = g_act2p + ((size_t)b * (HID_ / 2) + cp0 + pl) * HW_;
    #pragma unroll
    for (int j = 0; j < 7; j++) {
        uint32_t pk[4];
        #pragma unroll
        for (int c2 = 0; c2 < 4; c2++) {
            float v0 = __low2float(acc[j][c2]);
            float v1 = __high2float(acc[j][c2]);
            float a0 = siluf_(fmaf(v0, inv0, base0));
            float a1 = siluf_(fmaf(v1, inv1, base1));
            ls0 += a0; ls1 += a1;
            pk[c2] = pack2h(a0, a1);
        }
        *(uint4*)(op + (r0 + j) * 28 + cb) = make_uint4(pk[0], pk[1], pk[2], pk[3]);
    }
    part[pl][patch] = make_float2(ls0, ls1);
    __syncthreads();
    if (t < 16) {
        int p2 = t >> 1, hi = t & 1;
        float s = 0.f;
        #pragma unroll
        for (int i = 0; i < 28; i++) s += hi ? part[p2][i].y : part[p2][i].x;
        g_s[b * HID_ + 2 * (cp0 + p2) + hi] = s * (1.f / 784.f);
    }
}

// ============================================================
// Kernel 3: SE first layer -> g_zv   grid=64 block=256
// ============================================================
__global__ void k_sez(const float* __restrict__ w1, const float* __restrict__ b1) {
    int b = blockIdx.x, t = threadIdx.x, lane = t & 31, w = t >> 5;
    __shared__ float sv[HID_];
    for (int i = t; i < HID_; i += 256) sv[i] = g_s[b * HID_ + i];
    __syncthreads();
    #pragma unroll
    for (int i = 0; i < 3; i++) {
        int r = w + 8 * i;
        float s = 0.f;
        for (int c = lane; c < HID_; c += 32) s = fmaf(sv[c], w1[r * HID_ + c], s);
        #pragma unroll
        for (int o = 16; o; o >>= 1) s += __shfl_xor_sync(0xffffffffu, s, o);
        if (!lane) g_zv[b * RED_ + r] = siluf_(s + b1[r]);
    }
}

// ============================================================
// Kernel 4: SE second layer + mix pointwise weights + fold scale (f16x2)
// ============================================================
__global__ void k_wpw(const float* __restrict__ pw,
                      const float* __restrict__ w2, const float* __restrict__ b2) {
    int t = threadIdx.x, lane = t & 31, ty = t >> 5;
    int o = blockIdx.y * 8 + ty;
    int cp = blockIdx.x * 32 + lane;
    __shared__ float rws[B_][NE_];
    __shared__ float zvs[B_][RED_];
    __shared__ float scs[B_][64];

    for (int i = t; i < B_ * NE_; i += 256) rws[i >> 2][i & 3] = g_rw[i];
    for (int i = t; i < B_ * RED_; i += 256) zvs[i / RED_][i % RED_] = g_zv[i];
    __syncthreads();
    for (int idx = t; idx < B_ * 64; idx += 256) {
        int bb2 = idx >> 6, j = idx & 63;
        int c = blockIdx.x * 64 + j;
        float a = b2[c];
        #pragma unroll
        for (int r = 0; r < RED_; r++) a = fmaf(zvs[bb2][r], w2[c * RED_ + r], a);
        scs[bb2][j] = sigmoidf_(a);
    }
    __syncthreads();

    float p0[NE_], p1[NE_];
    #pragma unroll
    for (int e = 0; e < NE_; e++) {
        float2 v = *(const float2*)(pw + (size_t)(e * COUT_ + o) * HID_ + 2 * cp);
        p0[e] = v.x; p1[e] = v.y;
    }
    int jl = lane * 2;
    for (int b = 0; b < B_; b++) {
        float w0 = 0.f, w1v = 0.f;
        #pragma unroll
        for (int e = 0; e < NE_; e++) {
            w0  = fmaf(rws[b][e], p0[e], w0);
            w1v = fmaf(rws[b][e], p1[e], w1v);
        }
        g_wpwp[(size_t)(b * COUT_ + o) * (HID_ / 2) + cp] =
            pack2h(w0 * scs[b][jl], w1v * scs[b][jl + 1]);
    }
}

// ============================================================
// Kernel 5: pointwise GEMM (f16 mma) + BN3 + residual
// grid=(9,64) block=256  BM=96 BN=96 BK=64
// ============================================================
__global__ void k_pw(const float* __restrict__ x,
                     const float* __restrict__ gg, const float* __restrict__ bb,
                     const float* __restrict__ mm, const float* __restrict__ vv,
                     float* __restrict__ out) {
    __shared__ uint32_t ws[96][36];
    __shared__ uint32_t xs[32][104];
    int b = blockIdx.y, n0 = blockIdx.x * 96;
    int t = threadIdx.x, lane = t & 31, wid = t >> 5;
    int gid = lane >> 2, tig = lane & 3;
    int wm = wid >> 2, wn = wid & 3;

    float acc[3][3][4] = {};
    const uint32_t* wp = g_wpwp + (size_t)b * COUT_ * (HID_ / 2);
    const uint32_t* ap = g_act2p + (size_t)b * (HID_ / 2) * HW_;

    for (int k0p = 0; k0p < HID_ / 2; k0p += 32) {
        for (int i = t; i < 3072; i += 256) {
            int m = i >> 5, kp = i & 31;
            ws[m][kp] = wp[m * (HID_ / 2) + k0p + kp];
        }
        for (int i = t; i < 3072; i += 256) {
            int kp = i / 96, n = i % 96;
            int col = n0 + n;
            xs[kp][n] = (col < HW_) ? ap[(k0p + kp) * HW_ + col] : 0u;
        }
        __syncthreads();
        #pragma unroll
        for (int s = 0; s < 4; s++) {
            int kp = s * 8 + tig;
            uint32_t A[3][4];
            #pragma unroll
            for (int mi = 0; mi < 3; mi++) {
                int m = wm * 48 + mi * 16 + gid;
                A[mi][0] = ws[m][kp];     A[mi][1] = ws[m + 8][kp];
                A[mi][2] = ws[m][kp + 4]; A[mi][3] = ws[m + 8][kp + 4];
            }
            #pragma unroll
            for (int ni = 0; ni < 3; ni++) {
                int n = wn * 24 + ni * 8 + gid;
                uint32_t b0 = xs[kp][n], b1 = xs[kp + 4][n];
                #pragma unroll
                for (int mi = 0; mi < 3; mi++)
                    mma_f16(acc[mi][ni], A[mi][0], A[mi][1], A[mi][2], A[mi][3], b0, b1);
            }
        }
        __syncthreads();
    }

    #pragma unroll
    for (int mi = 0; mi < 3; mi++) {
        int oA = wm * 48 + mi * 16 + gid;
        int oB = oA + 8;
        float invA = gg[oA] * rsqrtf(vv[oA] + EPSBN), baseA = bb[oA] - mm[oA] * invA;
        float invB = gg[oB] * rsqrtf(vv[oB] + EPSBN), baseB = bb[oB] - mm[oB] * invB;
        #pragma unroll
        for (int ni = 0; ni < 3; ni++) {
            int col = n0 + wn * 24 + ni * 8 + tig * 2;
            if (col < HW_) {
                size_t iA = (size_t)(b * COUT_ + oA) * HW_ + col;
                size_t iB = (size_t)(b * COUT_ + oB) * HW_ + col;
                float2 rA = *(const float2*)(x + iA);
                float2 rB = *(const float2*)(x + iB);
                *(float2*)(out + iA) = make_float2(fmaf(acc[mi][ni][0], invA, baseA) + rA.x,
                                                   fmaf(acc[mi][ni][1], invA, baseA) + rA.y);
                *(float2*)(out + iB) = make_float2(fmaf(acc[mi][ni][2], invB, baseB) + rB.x,
                                                   fmaf(acc[mi][ni][3], invB, baseB) + rB.y);
            }
        }
    }
}

// ============================================================
extern "C" void kernel_launch(void* const* d_in, const int* in_sizes, int n_in,
                              void* d_out, int out_size) {
    const float* x     = (const float*)d_in[0];
    const float* r_w1  = (const float*)d_in[1];
    const float* r_b1  = (const float*)d_in[2];
    const float* r_w2  = (const float*)d_in[3];
    const float* r_b2  = (const float*)d_in[4];
    const float* exp_w = (const float*)d_in[5];
    const float* bn1_g = (const float*)d_in[6];
    const float* bn1_b = (const float*)d_in[7];
    const float* bn1_m = (const float*)d_in[8];
    const float* bn1_v = (const float*)d_in[9];
    const float* dw_w  = (const float*)d_in[10];
    const float* bn2_g = (const float*)d_in[11];
    const float* bn2_b = (const float*)d_in[12];
    const float* bn2_m = (const float*)d_in[13];
    const float* bn2_v = (const float*)d_in[14];
    const float* se_w1 = (const float*)d_in[15];
    const float* se_b1 = (const float*)d_in[16];
    const float* se_w2 = (const float*)d_in[17];
    const float* se_b2 = (const float*)d_in[18];
    const float* pw_w  = (const float*)d_in[19];
    const float* bn3_g = (const float*)d_in[20];
    const float* bn3_b = (const float*)d_in[21];
    const float* bn3_m = (const float*)d_in[22];
    const float* bn3_v = (const float*)d_in[23];
    float* out = (float*)d_out;

    k_pool  <<<dim3(6, B_), 256>>>(x);
    k_cvtw  <<<108, 256>>>(exp_w);
    k_rmlp  <<<B_, 32>>>(r_w1, r_b1, r_w2, r_b2);
    k_expand<<<dim3(9, B_), 256>>>(bn1_g, bn1_b, bn1_m, bn1_v);
    k_dw    <<<dim3(36, B_), 224>>>(dw_w, bn2_g, bn2_b, bn2_m, bn2_v);
    k_sez   <<<B_, 256>>>(se_w1, se_b1);
    k_wpw   <<<dim3(9, 12), 256>>>(pw_w, se_w2, se_b2);
    k_pw    <<<dim3(9, B_), 256>>>(x, bn3_g, bn3_b, bn3_m, bn3_v, out);
}

// round 13
// speedup vs baseline: 1.5934x; 1.0250x over previous
#include <cuda_runtime.h>
#include <cuda_fp16.h>
#include <cstdint>

#define B_    64
#define CIN_  96
#define HW_   784
#define HID_  576
#define NE_   4
#define RED_  24
#define RHID_ 24
#define COUT_ 96
#define EPSBN 1e-3f

// ---- scratch (device globals) ----
__device__ float    g_pool[B_ * CIN_];
__device__ float    g_rw  [B_ * NE_];
__device__ float    g_s   [B_ * HID_];
__device__ float    g_zv  [B_ * RED_];
__device__ __align__(16) uint32_t g_xp  [B_ * (CIN_ / 2) * HW_];     // x as f16x2 k-pairs
__device__ __align__(16) uint32_t g_wp  [HID_ * (CIN_ / 2)];         // exp_w f16x2, rows PERMUTED
__device__ __align__(16) uint32_t g_wpwp [B_ * COUT_ * (HID_ / 2)];  // f16x2 pairs along c
__device__ __align__(16) uint32_t g_act1p[B_ * (HID_ / 2) * HW_];    // f16x2 (ch even, ch odd)/pixel
__device__ __align__(16) uint32_t g_act2p[B_ * (HID_ / 2) * HW_];    // f16x2 (ch even, ch odd)/pixel

// silu(v) = h + h*tanh(h), h = v/2 — ONE scalar MUFU
__device__ __forceinline__ float siluf_(float v) {
    float h = 0.5f * v;
    float t; asm("tanh.approx.f32 %0, %1;" : "=f"(t) : "f"(h));
    return fmaf(h, t, h);
}
// sigmoid(v) = 0.5 + 0.5*tanh(v/2) — ONE scalar MUFU
__device__ __forceinline__ float sigmoidf_(float v) {
    float t; asm("tanh.approx.f32 %0, %1;" : "=f"(t) : "f"(0.5f * v));
    return fmaf(0.5f, t, 0.5f);
}

__device__ __forceinline__ uint32_t pack2h(float lo, float hi) {
    uint32_t r; asm("cvt.rn.f16x2.f32 %0, %1, %2;" : "=r"(r) : "f"(hi), "f"(lo)); return r;
}

__device__ __forceinline__ void mma_f16(float* d,
        uint32_t a0, uint32_t a1, uint32_t a2, uint32_t a3,
        uint32_t b0, uint32_t b1) {
    asm volatile(
        "mma.sync.aligned.m16n8k16.row.col.f32.f16.f16.f32 "
        "{%0,%1,%2,%3}, {%4,%5,%6,%7}, {%8,%9}, {%0,%1,%2,%3};\n"
        : "+f"(d[0]), "+f"(d[1]), "+f"(d[2]), "+f"(d[3])
        : "r"(a0), "r"(a1), "r"(a2), "r"(a3), "r"(b0), "r"(b1));
}

// ============================================================
// Kernel 0a: global average pool + pack x into f16x2 k-pairs
// ============================================================
__global__ void k_pool(const float* __restrict__ x) {
    int b = blockIdx.y, t = threadIdx.x, lane = t & 31, w = t >> 5;
    int c0 = blockIdx.x * 16 + w * 2;
    int cp = c0 >> 1;
    const float4* p0 = (const float4*)(x + (size_t)(b * CIN_ + c0) * HW_);
    const float4* p1 = (const float4*)(x + (size_t)(b * CIN_ + c0 + 1) * HW_);
    uint4* op = (uint4*)(g_xp + ((size_t)b * (CIN_ / 2) + cp) * HW_);
    float s0 = 0.f, s1 = 0.f;
    for (int i = lane; i < 196; i += 32) {
        float4 a = p0[i];
        float4 c = p1[i];
        s0 += (a.x + a.y) + (a.z + a.w);
        s1 += (c.x + c.y) + (c.z + c.w);
        op[i] = make_uint4(pack2h(a.x, c.x), pack2h(a.y, c.y),
                           pack2h(a.z, c.z), pack2h(a.w, c.w));
    }
    #pragma unroll
    for (int o = 16; o; o >>= 1) {
        s0 += __shfl_xor_sync(0xffffffffu, s0, o);
        s1 += __shfl_xor_sync(0xffffffffu, s1, o);
    }
    if (!lane) {
        g_pool[b * CIN_ + c0]     = s0 * (1.f / 784.f);
        g_pool[b * CIN_ + c0 + 1] = s1 * (1.f / 784.f);
    }
}

// ============================================================
// Kernel 0c: convert exp_w to f16x2 with PERMUTED rows
// ============================================================
__global__ void k_cvtw(const float* __restrict__ w) {
    int idx = blockIdx.x * 256 + threadIdx.x;
    int m = idx / 48, kp = idx % 48;
    int ch = (m & ~15) + 2 * (m & 7) + ((m >> 3) & 1);
    const float* wr = w + ch * CIN_ + 2 * kp;
    g_wp[idx] = pack2h(wr[0], wr[1]);
}

// ============================================================
// Kernel 0b: routing MLP + softmax  grid=64 block=32
// ============================================================
__global__ void k_rmlp(const float* __restrict__ w1, const float* __restrict__ b1,
                       const float* __restrict__ w2, const float* __restrict__ b2) {
    int b = blockIdx.x, lane = threadIdx.x;
    __shared__ float pool[CIN_];
    __shared__ float hdn[RHID_];
    __shared__ float lg[NE_];
    for (int i = lane; i < CIN_; i += 32) pool[i] = g_pool[b * CIN_ + i];
    __syncwarp();
    if (lane < RHID_) {
        float a = b1[lane];
        for (int c = 0; c < CIN_; c++) a = fmaf(pool[c], w1[lane * CIN_ + c], a);
        hdn[lane] = fmaxf(a, 0.f);
    }
    __syncwarp();
    if (lane < NE_) {
        float a = b2[lane];
        #pragma unroll
        for (int j = 0; j < RHID_; j++) a = fmaf(hdn[j], w2[lane * RHID_ + j], a);
        lg[lane] = a;
    }
    __syncwarp();
    if (lane == 0) {
        float mx = fmaxf(fmaxf(lg[0], lg[1]), fmaxf(lg[2], lg[3]));
        float e[4], s = 0.f;
        #pragma unroll
        for (int i = 0; i < 4; i++) { e[i] = __expf(lg[i] - mx); s += e[i]; }
        float inv = 1.f / s;
        #pragma unroll
        for (int i = 0; i < 4; i++) g_rw[b * NE_ + i] = e[i] * inv;
    }
}

// ============================================================
// Kernel 1: expand 1x1 GEMM (f16 mma) + BN1 + SiLU -> act1p
// grid=(9,64) block=256 — double-buffered cp.async pipeline over 7 hw-subtiles
// W staged through xs[1] then hoisted to registers
// ============================================================
__global__ void k_expand(const float* __restrict__ gg, const float* __restrict__ bb,
                         const float* __restrict__ mm, const float* __restrict__ vv) {
    __shared__ uint32_t xs[2][48][120];          // 45 KB; xs[1] doubles as W staging
    int b = blockIdx.y, o0 = blockIdx.x * 64;
    int t = threadIdx.x, lane = t & 31, wid = t >> 5;
    int gid = lane >> 2, tig = lane & 3;
    int wm = wid >> 1, wn = wid & 1;

    uint32_t* wsf = &xs[1][0][0];                // W staging: 64 rows x stride 52
    for (int i = t; i < 768; i += 256) {
        int m = i / 12, q = i % 12;
        *(uint4*)&wsf[m * 52 + 4 * q] = *(const uint4*)(g_wp + (o0 + m) * 48 + 4 * q);
    }
    __syncthreads();

    int m = wm * 16 + gid;
    uint32_t A[6][4];
    #pragma unroll
    for (int s = 0; s < 6; s++) {
        int kp = s * 8 + tig;
        A[s][0] = wsf[m * 52 + kp];       A[s][1] = wsf[(m + 8) * 52 + kp];
        A[s][2] = wsf[m * 52 + kp + 4];   A[s][3] = wsf[(m + 8) * 52 + kp + 4];
    }
    __syncthreads();                              // xs[1] now free for pipeline

    int ch0 = o0 + wm * 16 + 2 * gid;
    int ch1 = ch0 + 1;
    float inv0 = gg[ch0] * rsqrtf(vv[ch0] + EPSBN), base0 = bb[ch0] - mm[ch0] * inv0;
    float inv1 = gg[ch1] * rsqrtf(vv[ch1] + EPSBN), base1 = bb[ch1] - mm[ch1] * inv1;
    uint32_t* op = g_act1p + ((size_t)b * (HID_ / 2) + (ch0 >> 1)) * HW_;
    const uint32_t* xpb0 = g_xp + (size_t)b * (CIN_ / 2) * HW_;

    int kp0 = t / 28, q0 = t % 28;

    auto fill = [&](int hwt, int buf) {
        const uint32_t* xpb = xpb0 + hwt * 112;
        int kp = kp0, q = q0;
        #pragma unroll
        for (int it = 0; it < 6; it++) {
            if (t + it * 256 < 1344) {
                uint32_t saddr = (uint32_t)__cvta_generic_to_shared(&xs[buf][kp][4 * q]);
                asm volatile("cp.async.cg.shared.global [%0], [%1], 16;\n"
                             :: "r"(saddr), "l"(xpb + kp * HW_ + 4 * q) : "memory");
            }
            q += 4; kp += 9;
            if (q >= 28) { q -= 28; kp++; }
        }
        asm volatile("cp.async.commit_group;\n" ::: "memory");
    };

    fill(0, 0);
    asm volatile("cp.async.wait_group 0;\n" ::: "memory");
    __syncthreads();

    for (int hwt = 0; hwt < 7; hwt++) {
        int cur = hwt & 1;
        if (hwt < 6) fill(hwt + 1, cur ^ 1);      // async: overlaps MMA below

        float acc[7][4] = {};
        #pragma unroll
        for (int s = 0; s < 6; s++) {
            int kp = s * 8 + tig;
            #pragma unroll
            for (int ni = 0; ni < 7; ni++) {
                int n = wn * 56 + ni * 8 + gid;
                mma_f16(acc[ni], A[s][0], A[s][1], A[s][2], A[s][3],
                        xs[cur][kp][n], xs[cur][kp + 4][n]);
            }
        }

        int hw0 = hwt * 112;
        #pragma unroll
        for (int ni = 0; ni < 7; ni++) {
            int n = hw0 + wn * 56 + ni * 8 + tig * 2;
            float a0v = siluf_(fmaf(acc[ni][0], inv0, base0));
            float a1v = siluf_(fmaf(acc[ni][1], inv0, base0));
            float a2v = siluf_(fmaf(acc[ni][2], inv1, base1));
            float a3v = siluf_(fmaf(acc[ni][3], inv1, base1));
            *(uint2*)(op + n) = make_uint2(pack2h(a0v, a2v), pack2h(a1v, a3v));
        }

        if (hwt < 6) {
            asm volatile("cp.async.wait_group 0;\n" ::: "memory");
            __syncthreads();
        }
    }
}

// ============================================================
// Kernel 2: MoE depthwise 5x5 HFMA2 + BN2 + SiLU + SE pool
// grid=(36,64) block=224
// ============================================================
#define TSTRIDE 1064
__global__ void __launch_bounds__(224, 4) k_dw(
                     const float* __restrict__ dw,
                     const float* __restrict__ gg, const float* __restrict__ bb,
                     const float* __restrict__ mm, const float* __restrict__ vv) {
    int b = blockIdx.y, t = threadIdx.x;
    int cp0 = blockIdx.x * 8;
    __shared__ __half2 tile[8 * TSTRIDE];
    __shared__ __half2 kern[8][25];
    __shared__ float rwv[NE_];
    __shared__ float2 part[8][28];

    if (t < NE_) rwv[t] = g_rw[b * NE_ + t];
    const uint32_t* in = g_act1p + ((size_t)b * (HID_ / 2) + cp0) * HW_;
    for (int idx = t; idx < 8192; idx += 224) {
        int i = idx >> 10, p = idx & 1023;
        int r = p >> 5, c = p & 31;
        int rr = r - 2, cc = c - 2;
        bool ok = (rr >= 0 && rr < 28 && cc >= 0 && cc < 28);
        uint32_t wv = ok ? in[(size_t)i * HW_ + rr * 28 + cc] : 0u;
        *(uint32_t*)&tile[i * TSTRIDE + r * 33 + c] = wv;
    }
    __syncthreads();
    if (t < 200) {
        int pl = t / 25, kk = t % 25;
        int ch = 2 * (cp0 + pl);
        float s0 = 0.f, s1 = 0.f;
        #pragma unroll
        for (int e = 0; e < NE_; e++) {
            s0 = fmaf(rwv[e], dw[(e * HID_ + ch)     * 25 + kk], s0);
            s1 = fmaf(rwv[e], dw[(e * HID_ + ch + 1) * 25 + kk], s1);
        }
        kern[pl][kk] = __floats2half2_rn(s0, s1);
    }
    __syncthreads();

    int pl = t / 28;
    int patch = t % 28;
    int rg = patch / 7, cg = patch % 7;
    int r0 = rg * 7, cb = cg * 4;
    const __half2* tp = tile + pl * TSTRIDE;

    __half2 kr[25];
    #pragma unroll
    for (int i = 0; i < 25; i++) kr[i] = kern[pl][i];

    __half2 acc[7][4];
    #pragma unroll
    for (int j = 0; j < 7; j++)
        #pragma unroll
        for (int c2 = 0; c2 < 4; c2++) acc[j][c2] = __floats2half2_rn(0.f, 0.f);

    #pragma unroll
    for (int u = 0; u < 11; u++) {
        __half2 w8[8];
        #pragma unroll
        for (int wj = 0; wj < 8; wj++) w8[wj] = tp[(r0 + u) * 33 + cb + wj];
        #pragma unroll
        for (int j = 0; j < 7; j++) {
            if (u >= j && u <= j + 4) {
                int k = u - j;
                #pragma unroll
                for (int c2 = 0; c2 < 4; c2++)
                    #pragma unroll
                    for (int w2 = 0; w2 < 5; w2++)
                        acc[j][c2] = __hfma2(w8[c2 + w2], kr[k * 5 + w2], acc[j][c2]);
            }
        }
    }

    int ch0 = 2 * (cp0 + pl), ch1 = ch0 + 1;
    float inv0 = gg[ch0] * rsqrtf(vv[ch0] + EPSBN), base0 = bb[ch0] - mm[ch0] * inv0;
    float inv1 = gg[ch1] * rsqrtf(vv[ch1] + EPSBN), base1 = bb[ch1] - mm[ch1] * inv1;
    float ls0 = 0.f, ls1 = 0.f;
    uint32_t* op = g_act2p + ((size_t)b * (HID_ / 2) + cp0 + pl) * HW_;
    #pragma unroll
    for (int j = 0; j < 7; j++) {
        uint32_t pk[4];
        #pragma unroll
        for (int c2 = 0; c2 < 4; c2++) {
            float v0 = __low2float(acc[j][c2]);
            float v1 = __high2float(acc[j][c2]);
            float a0 = siluf_(fmaf(v0, inv0, base0));
            float a1 = siluf_(fmaf(v1, inv1, base1));
            ls0 += a0; ls1 += a1;
            pk[c2] = pack2h(a0, a1);
        }
        *(uint4*)(op + (r0 + j) * 28 + cb) = make_uint4(pk[0], pk[1], pk[2], pk[3]);
    }
    part[pl][patch] = make_float2(ls0, ls1);
    __syncthreads();
    if (t < 16) {
        int p2 = t >> 1, hi = t & 1;
        float s = 0.f;
        #pragma unroll
        for (int i = 0; i < 28; i++) s += hi ? part[p2][i].y : part[p2][i].x;
        g_s[b * HID_ + 2 * (cp0 + p2) + hi] = s * (1.f / 784.f);
    }
}

// ============================================================
// Kernel 3: SE first layer -> g_zv   grid=64 block=256
// ============================================================
__global__ void k_sez(const float* __restrict__ w1, const float* __restrict__ b1) {
    int b = blockIdx.x, t = threadIdx.x, lane = t & 31, w = t >> 5;
    __shared__ float sv[HID_];
    for (int i = t; i < HID_; i += 256) sv[i] = g_s[b * HID_ + i];
    __syncthreads();
    #pragma unroll
    for (int i = 0; i < 3; i++) {
        int r = w + 8 * i;
        float s = 0.f;
        for (int c = lane; c < HID_; c += 32) s = fmaf(sv[c], w1[r * HID_ + c], s);
        #pragma unroll
        for (int o = 16; o; o >>= 1) s += __shfl_xor_sync(0xffffffffu, s, o);
        if (!lane) g_zv[b * RED_ + r] = siluf_(s + b1[r]);
    }
}

// ============================================================
// Kernel 4: SE second layer + mix pointwise weights + fold scale (f16x2)
// ============================================================
__global__ void k_wpw(const float* __restrict__ pw,
                      const float* __restrict__ w2, const float* __restrict__ b2) {
    int t = threadIdx.x, lane = t & 31, ty = t >> 5;
    int o = blockIdx.y * 8 + ty;
    int cp = blockIdx.x * 32 + lane;
    __shared__ float rws[B_][NE_];
    __shared__ float zvs[B_][RED_];
    __shared__ float scs[B_][64];

    for (int i = t; i < B_ * NE_; i += 256) rws[i >> 2][i & 3] = g_rw[i];
    for (int i = t; i < B_ * RED_; i += 256) zvs[i / RED_][i % RED_] = g_zv[i];
    __syncthreads();
    for (int idx = t; idx < B_ * 64; idx += 256) {
        int bb2 = idx >> 6, j = idx & 63;
        int c = blockIdx.x * 64 + j;
        float a = b2[c];
        #pragma unroll
        for (int r = 0; r < RED_; r++) a = fmaf(zvs[bb2][r], w2[c * RED_ + r], a);
        scs[bb2][j] = sigmoidf_(a);
    }
    __syncthreads();

    float p0[NE_], p1[NE_];
    #pragma unroll
    for (int e = 0; e < NE_; e++) {
        float2 v = *(const float2*)(pw + (size_t)(e * COUT_ + o) * HID_ + 2 * cp);
        p0[e] = v.x; p1[e] = v.y;
    }
    int jl = lane * 2;
    for (int b = 0; b < B_; b++) {
        float w0 = 0.f, w1v = 0.f;
        #pragma unroll
        for (int e = 0; e < NE_; e++) {
            w0  = fmaf(rws[b][e], p0[e], w0);
            w1v = fmaf(rws[b][e], p1[e], w1v);
        }
        g_wpwp[(size_t)(b * COUT_ + o) * (HID_ / 2) + cp] =
            pack2h(w0 * scs[b][jl], w1v * scs[b][jl + 1]);
    }
}

// ============================================================
// Kernel 5: pointwise GEMM (f16 mma) + BN3 + residual
// grid=(9,64) block=256  BM=96 BN=96 BK=64
// ============================================================
__global__ void k_pw(const float* __restrict__ x,
                     const float* __restrict__ gg, const float* __restrict__ bb,
                     const float* __restrict__ mm, const float* __restrict__ vv,
                     float* __restrict__ out) {
    __shared__ uint32_t ws[96][36];
    __shared__ uint32_t xs[32][104];
    int b = blockIdx.y, n0 = blockIdx.x * 96;
    int t = threadIdx.x, lane = t & 31, wid = t >> 5;
    int gid = lane >> 2, tig = lane & 3;
    int wm = wid >> 2, wn = wid & 3;

    float acc[3][3][4] = {};
    const uint32_t* wp = g_wpwp + (size_t)b * COUT_ * (HID_ / 2);
    const uint32_t* ap = g_act2p + (size_t)b * (HID_ / 2) * HW_;

    for (int k0p = 0; k0p < HID_ / 2; k0p += 32) {
        for (int i = t; i < 3072; i += 256) {
            int m = i >> 5, kp = i & 31;
            ws[m][kp] = wp[m * (HID_ / 2) + k0p + kp];
        }
        for (int i = t; i < 3072; i += 256) {
            int kp = i / 96, n = i % 96;
            int col = n0 + n;
            xs[kp][n] = (col < HW_) ? ap[(k0p + kp) * HW_ + col] : 0u;
        }
        __syncthreads();
        #pragma unroll
        for (int s = 0; s < 4; s++) {
            int kp = s * 8 + tig;
            uint32_t A[3][4];
            #pragma unroll
            for (int mi = 0; mi < 3; mi++) {
                int m = wm * 48 + mi * 16 + gid;
                A[mi][0] = ws[m][kp];     A[mi][1] = ws[m + 8][kp];
                A[mi][2] = ws[m][kp + 4]; A[mi][3] = ws[m + 8][kp + 4];
            }
            #pragma unroll
            for (int ni = 0; ni < 3; ni++) {
                int n = wn * 24 + ni * 8 + gid;
                uint32_t b0 = xs[kp][n], b1 = xs[kp + 4][n];
                #pragma unroll
                for (int mi = 0; mi < 3; mi++)
                    mma_f16(acc[mi][ni], A[mi][0], A[mi][1], A[mi][2], A[mi][3], b0, b1);
            }
        }
        __syncthreads();
    }

    #pragma unroll
    for (int mi = 0; mi < 3; mi++) {
        int oA = wm * 48 + mi * 16 + gid;
        int oB = oA + 8;
        float invA = gg[oA] * rsqrtf(vv[oA] + EPSBN), baseA = bb[oA] - mm[oA] * invA;
        float invB = gg[oB] * rsqrtf(vv[oB] + EPSBN), baseB = bb[oB] - mm[oB] * invB;
        #pragma unroll
        for (int ni = 0; ni < 3; ni++) {
            int col = n0 + wn * 24 + ni * 8 + tig * 2;
            if (col < HW_) {
                size_t iA = (size_t)(b * COUT_ + oA) * HW_ + col;
                size_t iB = (size_t)(b * COUT_ + oB) * HW_ + col;
                float2 rA = *(const float2*)(x + iA);
                float2 rB = *(const float2*)(x + iB);
                *(float2*)(out + iA) = make_float2(fmaf(acc[mi][ni][0], invA, baseA) + rA.x,
                                                   fmaf(acc[mi][ni][1], invA, baseA) + rA.y);
                *(float2*)(out + iB) = make_float2(fmaf(acc[mi][ni][2], invB, baseB) + rB.x,
                                                   fmaf(acc[mi][ni][3], invB, baseB) + rB.y);
            }
        }
    }
}

// ============================================================
extern "C" void kernel_launch(void* const* d_in, const int* in_sizes, int n_in,
                              void* d_out, int out_size) {
    const float* x     = (const float*)d_in[0];
    const float* r_w1  = (const float*)d_in[1];
    const float* r_b1  = (const float*)d_in[2];
    const float* r_w2  = (const float*)d_in[3];
    const float* r_b2  = (const float*)d_in[4];
    const float* exp_w = (const float*)d_in[5];
    const float* bn1_g = (const float*)d_in[6];
    const float* bn1_b = (const float*)d_in[7];
    const float* bn1_m = (const float*)d_in[8];
    const float* bn1_v = (const float*)d_in[9];
    const float* dw_w  = (const float*)d_in[10];
    const float* bn2_g = (const float*)d_in[11];
    const float* bn2_b = (const float*)d_in[12];
    const float* bn2_m = (const float*)d_in[13];
    const float* bn2_v = (const float*)d_in[14];
    const float* se_w1 = (const float*)d_in[15];
    const float* se_b1 = (const float*)d_in[16];
    const float* se_w2 = (const float*)d_in[17];
    const float* se_b2 = (const float*)d_in[18];
    const float* pw_w  = (const float*)d_in[19];
    const float* bn3_g = (const float*)d_in[20];
    const float* bn3_b = (const float*)d_in[21];
    const float* bn3_m = (const float*)d_in[22];
    const float* bn3_v = (const float*)d_in[23];
    float* out = (float*)d_out;

    k_pool  <<<dim3(6, B_), 256>>>(x);
    k_cvtw  <<<108, 256>>>(exp_w);
    k_rmlp  <<<B_, 32>>>(r_w1, r_b1, r_w2, r_b2);
    k_expand<<<dim3(9, B_), 256>>>(bn1_g, bn1_b, bn1_m, bn1_v);
    k_dw    <<<dim3(36, B_), 224>>>(dw_w, bn2_g, bn2_b, bn2_m, bn2_v);
    k_sez   <<<B_, 256>>>(se_w1, se_b1);
    k_wpw   <<<dim3(9, 12), 256>>>(pw_w, se_w2, se_b2);
    k_pw    <<<dim3(9, B_), 256>>>(x, bn3_g, bn3_b, bn3_m, bn3_v, out);
}

// round 14
// speedup vs baseline: 1.8338x; 1.1509x over previous
#include <cuda_runtime.h>
#include <cuda_fp16.h>
#include <cstdint>

#define B_    64
#define CIN_  96
#define HW_   784
#define HID_  576
#define NE_   4
#define RED_  24
#define RHID_ 24
#define COUT_ 96
#define EPSBN 1e-3f

// ---- scratch (device globals) ----
__device__ float    g_pool[B_ * CIN_];
__device__ float    g_rw  [B_ * NE_];
__device__ float    g_s   [B_ * HID_];
__device__ float    g_zv  [B_ * RED_];
__device__ __align__(16) uint32_t g_xp  [B_ * (CIN_ / 2) * HW_];     // x as f16x2 k-pairs
__device__ __align__(16) uint32_t g_wp  [HID_ * (CIN_ / 2)];         // exp_w f16x2, rows PERMUTED
__device__ __align__(16) uint32_t g_wpwp [B_ * COUT_ * (HID_ / 2)];  // f16x2 pairs along c
__device__ __align__(16) uint32_t g_act1p[B_ * (HID_ / 2) * HW_];    // f16x2 (ch even, ch odd)/pixel
__device__ __align__(16) uint32_t g_act2p[B_ * (HID_ / 2) * HW_];    // f16x2 (ch even, ch odd)/pixel

// silu(v) = h + h*tanh(h), h = v/2 — ONE scalar MUFU
__device__ __forceinline__ float siluf_(float v) {
    float h = 0.5f * v;
    float t; asm("tanh.approx.f32 %0, %1;" : "=f"(t) : "f"(h));
    return fmaf(h, t, h);
}
// sigmoid(v) = 0.5 + 0.5*tanh(v/2) — ONE scalar MUFU
__device__ __forceinline__ float sigmoidf_(float v) {
    float t; asm("tanh.approx.f32 %0, %1;" : "=f"(t) : "f"(0.5f * v));
    return fmaf(0.5f, t, 0.5f);
}

__device__ __forceinline__ uint32_t pack2h(float lo, float hi) {
    uint32_t r; asm("cvt.rn.f16x2.f32 %0, %1, %2;" : "=r"(r) : "f"(hi), "f"(lo)); return r;
}

__device__ __forceinline__ void mma_f16(float* d,
        uint32_t a0, uint32_t a1, uint32_t a2, uint32_t a3,
        uint32_t b0, uint32_t b1) {
    asm volatile(
        "mma.sync.aligned.m16n8k16.row.col.f32.f16.f16.f32 "
        "{%0,%1,%2,%3}, {%4,%5,%6,%7}, {%8,%9}, {%0,%1,%2,%3};\n"
        : "+f"(d[0]), "+f"(d[1]), "+f"(d[2]), "+f"(d[3])
        : "r"(a0), "r"(a1), "r"(a2), "r"(a3), "r"(b0), "r"(b1));
}

// ============================================================
// Kernel 0a: global average pool + pack x into f16x2 k-pairs
// ============================================================
__global__ void k_pool(const float* __restrict__ x) {
    int b = blockIdx.y, t = threadIdx.x, lane = t & 31, w = t >> 5;
    int c0 = blockIdx.x * 16 + w * 2;
    int cp = c0 >> 1;
    const float4* p0 = (const float4*)(x + (size_t)(b * CIN_ + c0) * HW_);
    const float4* p1 = (const float4*)(x + (size_t)(b * CIN_ + c0 + 1) * HW_);
    uint4* op = (uint4*)(g_xp + ((size_t)b * (CIN_ / 2) + cp) * HW_);
    float s0 = 0.f, s1 = 0.f;
    for (int i = lane; i < 196; i += 32) {
        float4 a = p0[i];
        float4 c = p1[i];
        s0 += (a.x + a.y) + (a.z + a.w);
        s1 += (c.x + c.y) + (c.z + c.w);
        op[i] = make_uint4(pack2h(a.x, c.x), pack2h(a.y, c.y),
                           pack2h(a.z, c.z), pack2h(a.w, c.w));
    }
    #pragma unroll
    for (int o = 16; o; o >>= 1) {
        s0 += __shfl_xor_sync(0xffffffffu, s0, o);
        s1 += __shfl_xor_sync(0xffffffffu, s1, o);
    }
    if (!lane) {
        g_pool[b * CIN_ + c0]     = s0 * (1.f / 784.f);
        g_pool[b * CIN_ + c0 + 1] = s1 * (1.f / 784.f);
    }
}

// ============================================================
// Kernel 0c: convert exp_w to f16x2 with PERMUTED rows
// ============================================================
__global__ void k_cvtw(const float* __restrict__ w) {
    int idx = blockIdx.x * 256 + threadIdx.x;
    int m = idx / 48, kp = idx % 48;
    int ch = (m & ~15) + 2 * (m & 7) + ((m >> 3) & 1);
    const float* wr = w + ch * CIN_ + 2 * kp;
    g_wp[idx] = pack2h(wr[0], wr[1]);
}

// ============================================================
// Kernel 0b: routing MLP + softmax  grid=64 block=32
// ============================================================
__global__ void k_rmlp(const float* __restrict__ w1, const float* __restrict__ b1,
                       const float* __restrict__ w2, const float* __restrict__ b2) {
    int b = blockIdx.x, lane = threadIdx.x;
    __shared__ float pool[CIN_];
    __shared__ float hdn[RHID_];
    __shared__ float lg[NE_];
    for (int i = lane; i < CIN_; i += 32) pool[i] = g_pool[b * CIN_ + i];
    __syncwarp();
    if (lane < RHID_) {
        float a = b1[lane];
        for (int c = 0; c < CIN_; c++) a = fmaf(pool[c], w1[lane * CIN_ + c], a);
        hdn[lane] = fmaxf(a, 0.f);
    }
    __syncwarp();
    if (lane < NE_) {
        float a = b2[lane];
        #pragma unroll
        for (int j = 0; j < RHID_; j++) a = fmaf(hdn[j], w2[lane * RHID_ + j], a);
        lg[lane] = a;
    }
    __syncwarp();
    if (lane == 0) {
        float mx = fmaxf(fmaxf(lg[0], lg[1]), fmaxf(lg[2], lg[3]));
        float e[4], s = 0.f;
        #pragma unroll
        for (int i = 0; i < 4; i++) { e[i] = __expf(lg[i] - mx); s += e[i]; }
        float inv = 1.f / s;
        #pragma unroll
        for (int i = 0; i < 4; i++) g_rw[b * NE_ + i] = e[i] * inv;
    }
}

// ============================================================
// Kernel 1: expand 1x1 GEMM (f16 mma) + BN1 + SiLU -> act1p
// grid=(9,64) block=256 — double-buffered cp.async pipeline over 7 hw-subtiles
// ============================================================
__global__ void k_expand(const float* __restrict__ gg, const float* __restrict__ bb,
                         const float* __restrict__ mm, const float* __restrict__ vv) {
    __shared__ uint32_t xs[2][48][120];
    int b = blockIdx.y, o0 = blockIdx.x * 64;
    int t = threadIdx.x, lane = t & 31, wid = t >> 5;
    int gid = lane >> 2, tig = lane & 3;
    int wm = wid >> 1, wn = wid & 1;

    uint32_t* wsf = &xs[1][0][0];
    for (int i = t; i < 768; i += 256) {
        int m = i / 12, q = i % 12;
        *(uint4*)&wsf[m * 52 + 4 * q] = *(const uint4*)(g_wp + (o0 + m) * 48 + 4 * q);
    }
    __syncthreads();

    int m = wm * 16 + gid;
    uint32_t A[6][4];
    #pragma unroll
    for (int s = 0; s < 6; s++) {
        int kp = s * 8 + tig;
        A[s][0] = wsf[m * 52 + kp];       A[s][1] = wsf[(m + 8) * 52 + kp];
        A[s][2] = wsf[m * 52 + kp + 4];   A[s][3] = wsf[(m + 8) * 52 + kp + 4];
    }
    __syncthreads();

    int ch0 = o0 + wm * 16 + 2 * gid;
    int ch1 = ch0 + 1;
    float inv0 = gg[ch0] * rsqrtf(vv[ch0] + EPSBN), base0 = bb[ch0] - mm[ch0] * inv0;
    float inv1 = gg[ch1] * rsqrtf(vv[ch1] + EPSBN), base1 = bb[ch1] - mm[ch1] * inv1;
    uint32_t* op = g_act1p + ((size_t)b * (HID_ / 2) + (ch0 >> 1)) * HW_;
    const uint32_t* xpb0 = g_xp + (size_t)b * (CIN_ / 2) * HW_;

    int kp0 = t / 28, q0 = t % 28;

    auto fill = [&](int hwt, int buf) {
        const uint32_t* xpb = xpb0 + hwt * 112;
        int kp = kp0, q = q0;
        #pragma unroll
        for (int it = 0; it < 6; it++) {
            if (t + it * 256 < 1344) {
                uint32_t saddr = (uint32_t)__cvta_generic_to_shared(&xs[buf][kp][4 * q]);
                asm volatile("cp.async.cg.shared.global [%0], [%1], 16;\n"
                             :: "r"(saddr), "l"(xpb + kp * HW_ + 4 * q) : "memory");
            }
            q += 4; kp += 9;
            if (q >= 28) { q -= 28; kp++; }
        }
        asm volatile("cp.async.commit_group;\n" ::: "memory");
    };

    fill(0, 0);
    asm volatile("cp.async.wait_group 0;\n" ::: "memory");
    __syncthreads();

    for (int hwt = 0; hwt < 7; hwt++) {
        int cur = hwt & 1;
        if (hwt < 6) fill(hwt + 1, cur ^ 1);

        float acc[7][4] = {};
        #pragma unroll
        for (int s = 0; s < 6; s++) {
            int kp = s * 8 + tig;
            #pragma unroll
            for (int ni = 0; ni < 7; ni++) {
                int n = wn * 56 + ni * 8 + gid;
                mma_f16(acc[ni], A[s][0], A[s][1], A[s][2], A[s][3],
                        xs[cur][kp][n], xs[cur][kp + 4][n]);
            }
        }

        int hw0 = hwt * 112;
        #pragma unroll
        for (int ni = 0; ni < 7; ni++) {
            int n = hw0 + wn * 56 + ni * 8 + tig * 2;
            float a0v = siluf_(fmaf(acc[ni][0], inv0, base0));
            float a1v = siluf_(fmaf(acc[ni][1], inv0, base0));
            float a2v = siluf_(fmaf(acc[ni][2], inv1, base1));
            float a3v = siluf_(fmaf(acc[ni][3], inv1, base1));
            *(uint2*)(op + n) = make_uint2(pack2h(a0v, a2v), pack2h(a1v, a3v));
        }

        if (hwt < 6) {
            asm volatile("cp.async.wait_group 0;\n" ::: "memory");
            __syncthreads();
        }
    }
}

// ============================================================
// Kernel 2: MoE depthwise 5x5 HFMA2 + BN2 + SiLU + SE pool
// grid=(36,64) block=224
// ============================================================
#define TSTRIDE 1064
__global__ void __launch_bounds__(224, 4) k_dw(
                     const float* __restrict__ dw,
                     const float* __restrict__ gg, const float* __restrict__ bb,
                     const float* __restrict__ mm, const float* __restrict__ vv) {
    int b = blockIdx.y, t = threadIdx.x;
    int cp0 = blockIdx.x * 8;
    __shared__ __half2 tile[8 * TSTRIDE];
    __shared__ __half2 kern[8][25];
    __shared__ float rwv[NE_];
    __shared__ float2 part[8][28];

    if (t < NE_) rwv[t] = g_rw[b * NE_ + t];
    const uint32_t* in = g_act1p + ((size_t)b * (HID_ / 2) + cp0) * HW_;
    for (int idx = t; idx < 8192; idx += 224) {
        int i = idx >> 10, p = idx & 1023;
        int r = p >> 5, c = p & 31;
        int rr = r - 2, cc = c - 2;
        bool ok = (rr >= 0 && rr < 28 && cc >= 0 && cc < 28);
        uint32_t wv = ok ? in[(size_t)i * HW_ + rr * 28 + cc] : 0u;
        *(uint32_t*)&tile[i * TSTRIDE + r * 33 + c] = wv;
    }
    __syncthreads();
    if (t < 200) {
        int pl = t / 25, kk = t % 25;
        int ch = 2 * (cp0 + pl);
        float s0 = 0.f, s1 = 0.f;
        #pragma unroll
        for (int e = 0; e < NE_; e++) {
            s0 = fmaf(rwv[e], dw[(e * HID_ + ch)     * 25 + kk], s0);
            s1 = fmaf(rwv[e], dw[(e * HID_ + ch + 1) * 25 + kk], s1);
        }
        kern[pl][kk] = __floats2half2_rn(s0, s1);
    }
    __syncthreads();

    int pl = t / 28;
    int patch = t % 28;
    int rg = patch / 7, cg = patch % 7;
    int r0 = rg * 7, cb = cg * 4;
    const __half2* tp = tile + pl * TSTRIDE;

    __half2 kr[25];
    #pragma unroll
    for (int i = 0; i < 25; i++) kr[i] = kern[pl][i];

    __half2 acc[7][4];
    #pragma unroll
    for (int j = 0; j < 7; j++)
        #pragma unroll
        for (int c2 = 0; c2 < 4; c2++) acc[j][c2] = __floats2half2_rn(0.f, 0.f);

    #pragma unroll
    for (int u = 0; u < 11; u++) {
        __half2 w8[8];
        #pragma unroll
        for (int wj = 0; wj < 8; wj++) w8[wj] = tp[(r0 + u) * 33 + cb + wj];
        #pragma unroll
        for (int j = 0; j < 7; j++) {
            if (u >= j && u <= j + 4) {
                int k = u - j;
                #pragma unroll
                for (int c2 = 0; c2 < 4; c2++)
                    #pragma unroll
                    for (int w2 = 0; w2 < 5; w2++)
                        acc[j][c2] = __hfma2(w8[c2 + w2], kr[k * 5 + w2], acc[j][c2]);
            }
        }
    }

    int ch0 = 2 * (cp0 + pl), ch1 = ch0 + 1;
    float inv0 = gg[ch0] * rsqrtf(vv[ch0] + EPSBN), base0 = bb[ch0] - mm[ch0] * inv0;
    float inv1 = gg[ch1] * rsqrtf(vv[ch1] + EPSBN), base1 = bb[ch1] - mm[ch1] * inv1;
    float ls0 = 0.f, ls1 = 0.f;
    uint32_t* op = g_act2p + ((size_t)b * (HID_ / 2) + cp0 + pl) * HW_;
    #pragma unroll
    for (int j = 0; j < 7; j++) {
        uint32_t pk[4];
        #pragma unroll
        for (int c2 = 0; c2 < 4; c2++) {
            float v0 = __low2float(acc[j][c2]);
            float v1 = __high2float(acc[j][c2]);
            float a0 = siluf_(fmaf(v0, inv0, base0));
            float a1 = siluf_(fmaf(v1, inv1, base1));
            ls0 += a0; ls1 += a1;
            pk[c2] = pack2h(a0, a1);
        }
        *(uint4*)(op + (r0 + j) * 28 + cb) = make_uint4(pk[0], pk[1], pk[2], pk[3]);
    }
    part[pl][patch] = make_float2(ls0, ls1);
    __syncthreads();
    if (t < 16) {
        int p2 = t >> 1, hi = t & 1;
        float s = 0.f;
        #pragma unroll
        for (int i = 0; i < 28; i++) s += hi ? part[p2][i].y : part[p2][i].x;
        g_s[b * HID_ + 2 * (cp0 + p2) + hi] = s * (1.f / 784.f);
    }
}

// ============================================================
// Kernel 3: SE first layer -> g_zv   grid=64 block=256
// ============================================================
__global__ void k_sez(const float* __restrict__ w1, const float* __restrict__ b1) {
    int b = blockIdx.x, t = threadIdx.x, lane = t & 31, w = t >> 5;
    __shared__ float sv[HID_];
    for (int i = t; i < HID_; i += 256) sv[i] = g_s[b * HID_ + i];
    __syncthreads();
    #pragma unroll
    for (int i = 0; i < 3; i++) {
        int r = w + 8 * i;
        float s = 0.f;
        for (int c = lane; c < HID_; c += 32) s = fmaf(sv[c], w1[r * HID_ + c], s);
        #pragma unroll
        for (int o = 16; o; o >>= 1) s += __shfl_xor_sync(0xffffffffu, s, o);
        if (!lane) g_zv[b * RED_ + r] = siluf_(s + b1[r]);
    }
}

// ============================================================
// Kernel 4: SE second layer + mix pointwise weights + fold scale (f16x2)
// ============================================================
__global__ void k_wpw(const float* __restrict__ pw,
                      const float* __restrict__ w2, const float* __restrict__ b2) {
    int t = threadIdx.x, lane = t & 31, ty = t >> 5;
    int o = blockIdx.y * 8 + ty;
    int cp = blockIdx.x * 32 + lane;
    __shared__ float rws[B_][NE_];
    __shared__ float zvs[B_][RED_];
    __shared__ float scs[B_][64];

    for (int i = t; i < B_ * NE_; i += 256) rws[i >> 2][i & 3] = g_rw[i];
    for (int i = t; i < B_ * RED_; i += 256) zvs[i / RED_][i % RED_] = g_zv[i];
    __syncthreads();
    for (int idx = t; idx < B_ * 64; idx += 256) {
        int bb2 = idx >> 6, j = idx & 63;
        int c = blockIdx.x * 64 + j;
        float a = b2[c];
        #pragma unroll
        for (int r = 0; r < RED_; r++) a = fmaf(zvs[bb2][r], w2[c * RED_ + r], a);
        scs[bb2][j] = sigmoidf_(a);
    }
    __syncthreads();

    float p0[NE_], p1[NE_];
    #pragma unroll
    for (int e = 0; e < NE_; e++) {
        float2 v = *(const float2*)(pw + (size_t)(e * COUT_ + o) * HID_ + 2 * cp);
        p0[e] = v.x; p1[e] = v.y;
    }
    int jl = lane * 2;
    for (int b = 0; b < B_; b++) {
        float w0 = 0.f, w1v = 0.f;
        #pragma unroll
        for (int e = 0; e < NE_; e++) {
            w0  = fmaf(rws[b][e], p0[e], w0);
            w1v = fmaf(rws[b][e], p1[e], w1v);
        }
        g_wpwp[(size_t)(b * COUT_ + o) * (HID_ / 2) + cp] =
            pack2h(w0 * scs[b][jl], w1v * scs[b][jl + 1]);
    }
}

// ============================================================
// Kernel 5: pointwise GEMM (f16 mma) + BN3 + residual
// grid=(9,64) block=256  BM=96 BN=96 BK=64
// double-buffered cp.async over the 9 k-iterations
// ============================================================
__global__ void k_pw(const float* __restrict__ x,
                     const float* __restrict__ gg, const float* __restrict__ bb,
                     const float* __restrict__ mm, const float* __restrict__ vv,
                     float* __restrict__ out) {
    __shared__ uint32_t ws[2][96][36];
    __shared__ uint32_t xs[2][32][104];
    int b = blockIdx.y, n0 = blockIdx.x * 96;
    int t = threadIdx.x, lane = t & 31, wid = t >> 5;
    int gid = lane >> 2, tig = lane & 3;
    int wm = wid >> 2, wn = wid & 3;

    float acc[3][3][4] = {};
    const uint32_t* wp = g_wpwp + (size_t)b * COUT_ * (HID_ / 2);
    const uint32_t* ap = g_act2p + (size_t)b * (HID_ / 2) * HW_;

    auto fill = [&](int it9, int buf) {
        int k0p = it9 * 32;
        // W: 96 rows x 8 uint4 (32 kpairs)
        #pragma unroll
        for (int r = 0; r < 3; r++) {
            int i = t + r * 256;
            int m = i >> 3, q = i & 7;
            uint32_t saddr = (uint32_t)__cvta_generic_to_shared(&ws[buf][m][4 * q]);
            asm volatile("cp.async.cg.shared.global [%0], [%1], 16;\n"
                         :: "r"(saddr), "l"(wp + m * (HID_ / 2) + k0p + 4 * q) : "memory");
        }
        // X: 32 kpairs x 24 uint4 (96 cols), zero-fill beyond HW_
        #pragma unroll
        for (int r = 0; r < 3; r++) {
            int i = t + r * 256;
            int kp = i / 24, q = i % 24;
            int col = n0 + 4 * q;
            int ssz = (col < HW_) ? 16 : 0;
            uint32_t saddr = (uint32_t)__cvta_generic_to_shared(&xs[buf][kp][4 * q]);
            const uint32_t* src = ap + (size_t)(k0p + kp) * HW_ + ((col < HW_) ? col : 0);
            asm volatile("cp.async.cg.shared.global [%0], [%1], 16, %2;\n"
                         :: "r"(saddr), "l"(src), "r"(ssz) : "memory");
        }
        asm volatile("cp.async.commit_group;\n" ::: "memory");
    };

    fill(0, 0);
    asm volatile("cp.async.wait_group 0;\n" ::: "memory");
    __syncthreads();

    for (int it9 = 0; it9 < 9; it9++) {
        int cur = it9 & 1;
        if (it9 < 8) fill(it9 + 1, cur ^ 1);

        #pragma unroll
        for (int s = 0; s < 4; s++) {
            int kp = s * 8 + tig;
            uint32_t A[3][4];
            #pragma unroll
            for (int mi = 0; mi < 3; mi++) {
                int m = wm * 48 + mi * 16 + gid;
                A[mi][0] = ws[cur][m][kp];     A[mi][1] = ws[cur][m + 8][kp];
                A[mi][2] = ws[cur][m][kp + 4]; A[mi][3] = ws[cur][m + 8][kp + 4];
            }
            #pragma unroll
            for (int ni = 0; ni < 3; ni++) {
                int n = wn * 24 + ni * 8 + gid;
                uint32_t b0 = xs[cur][kp][n], b1 = xs[cur][kp + 4][n];
                #pragma unroll
                for (int mi = 0; mi < 3; mi++)
                    mma_f16(acc[mi][ni], A[mi][0], A[mi][1], A[mi][2], A[mi][3], b0, b1);
            }
        }

        if (it9 < 8) {
            asm volatile("cp.async.wait_group 0;\n" ::: "memory");
            __syncthreads();
        }
    }

    #pragma unroll
    for (int mi = 0; mi < 3; mi++) {
        int oA = wm * 48 + mi * 16 + gid;
        int oB = oA + 8;
        float invA = gg[oA] * rsqrtf(vv[oA] + EPSBN), baseA = bb[oA] - mm[oA] * invA;
        float invB = gg[oB] * rsqrtf(vv[oB] + EPSBN), baseB = bb[oB] - mm[oB] * invB;
        #pragma unroll
        for (int ni = 0; ni < 3; ni++) {
            int col = n0 + wn * 24 + ni * 8 + tig * 2;
            if (col < HW_) {
                size_t iA = (size_t)(b * COUT_ + oA) * HW_ + col;
                size_t iB = (size_t)(b * COUT_ + oB) * HW_ + col;
                float2 rA = *(const float2*)(x + iA);
                float2 rB = *(const float2*)(x + iB);
                *(float2*)(out + iA) = make_float2(fmaf(acc[mi][ni][0], invA, baseA) + rA.x,
                                                   fmaf(acc[mi][ni][1], invA, baseA) + rA.y);
                *(float2*)(out + iB) = make_float2(fmaf(acc[mi][ni][2], invB, baseB) + rB.x,
                                                   fmaf(acc[mi][ni][3], invB, baseB) + rB.y);
            }
        }
    }
}

// ============================================================
extern "C" void kernel_launch(void* const* d_in, const int* in_sizes, int n_in,
                              void* d_out, int out_size) {
    const float* x     = (const float*)d_in[0];
    const float* r_w1  = (const float*)d_in[1];
    const float* r_b1  = (const float*)d_in[2];
    const float* r_w2  = (const float*)d_in[3];
    const float* r_b2  = (const float*)d_in[4];
    const float* exp_w = (const float*)d_in[5];
    const float* bn1_g = (const float*)d_in[6];
    const float* bn1_b = (const float*)d_in[7];
    const float* bn1_m = (const float*)d_in[8];
    const float* bn1_v = (const float*)d_in[9];
    const float* dw_w  = (const float*)d_in[10];
    const float* bn2_g = (const float*)d_in[11];
    const float* bn2_b = (const float*)d_in[12];
    const float* bn2_m = (const float*)d_in[13];
    const float* bn2_v = (const float*)d_in[14];
    const float* se_w1 = (const float*)d_in[15];
    const float* se_b1 = (const float*)d_in[16];
    const float* se_w2 = (const float*)d_in[17];
    const float* se_b2 = (const float*)d_in[18];
    const float* pw_w  = (const float*)d_in[19];
    const float* bn3_g = (const float*)d_in[20];
    const float* bn3_b = (const float*)d_in[21];
    const float* bn3_m = (const float*)d_in[22];
    const float* bn3_v = (const float*)d_in[23];
    float* out = (float*)d_out;

    k_pool  <<<dim3(6, B_), 256>>>(x);
    k_cvtw  <<<108, 256>>>(exp_w);
    k_rmlp  <<<B_, 32>>>(r_w1, r_b1, r_w2, r_b2);
    k_expand<<<dim3(9, B_), 256>>>(bn1_g, bn1_b, bn1_m, bn1_v);
    k_dw    <<<dim3(36, B_), 224>>>(dw_w, bn2_g, bn2_b, bn2_m, bn2_v);
    k_sez   <<<B_, 256>>>(se_w1, se_b1);
    k_wpw   <<<dim3(9, 12), 256>>>(pw_w, se_w2, se_b2);
    k_pw    <<<dim3(9, B_), 256>>>(x, bn3_g, bn3_b, bn3_m, bn3_v, out);
}

// round 15
// speedup vs baseline: 1.9227x; 1.0485x over previous
#include <cuda_runtime.h>
#include <cuda_fp16.h>
#include <cstdint>

#define B_    64
#define CIN_  96
#define HW_   784
#define HID_  576
#define NE_   4
#define RED_  24
#define RHID_ 24
#define COUT_ 96
#define EPSBN 1e-3f

// ---- scratch (device globals) ----
__device__ float    g_pool[B_ * CIN_];
__device__ float    g_rw  [B_ * NE_];
__device__ float    g_s   [B_ * HID_];
__device__ float    g_zv  [B_ * RED_];
__device__ __align__(16) uint32_t g_xp  [B_ * (CIN_ / 2) * HW_];     // x as f16x2 k-pairs
__device__ __align__(16) uint32_t g_wp  [HID_ * (CIN_ / 2)];         // exp_w f16x2, rows PERMUTED
__device__ __align__(16) uint32_t g_wpwp [B_ * COUT_ * (HID_ / 2)];  // f16x2 pairs along c
__device__ __align__(16) uint32_t g_act1p[B_ * (HID_ / 2) * HW_];    // f16x2 (ch even, ch odd)/pixel
__device__ __align__(16) uint32_t g_act2p[B_ * (HID_ / 2) * HW_];    // f16x2 (ch even, ch odd)/pixel

// silu(v) = h + h*tanh(h), h = v/2 — ONE scalar MUFU
__device__ __forceinline__ float siluf_(float v) {
    float h = 0.5f * v;
    float t; asm("tanh.approx.f32 %0, %1;" : "=f"(t) : "f"(h));
    return fmaf(h, t, h);
}
// sigmoid(v) = 0.5 + 0.5*tanh(v/2) — ONE scalar MUFU
__device__ __forceinline__ float sigmoidf_(float v) {
    float t; asm("tanh.approx.f32 %0, %1;" : "=f"(t) : "f"(0.5f * v));
    return fmaf(0.5f, t, 0.5f);
}

__device__ __forceinline__ uint32_t pack2h(float lo, float hi) {
    uint32_t r; asm("cvt.rn.f16x2.f32 %0, %1, %2;" : "=r"(r) : "f"(hi), "f"(lo)); return r;
}

__device__ __forceinline__ void mma_f16(float* d,
        uint32_t a0, uint32_t a1, uint32_t a2, uint32_t a3,
        uint32_t b0, uint32_t b1) {
    asm volatile(
        "mma.sync.aligned.m16n8k16.row.col.f32.f16.f16.f32 "
        "{%0,%1,%2,%3}, {%4,%5,%6,%7}, {%8,%9}, {%0,%1,%2,%3};\n"
        : "+f"(d[0]), "+f"(d[1]), "+f"(d[2]), "+f"(d[3])
        : "r"(a0), "r"(a1), "r"(a2), "r"(a3), "r"(b0), "r"(b1));
}

// ============================================================
// Kernel 0a: global average pool + pack x into f16x2 k-pairs
// ============================================================
__global__ void k_pool(const float* __restrict__ x) {
    int b = blockIdx.y, t = threadIdx.x, lane = t & 31, w = t >> 5;
    int c0 = blockIdx.x * 16 + w * 2;
    int cp = c0 >> 1;
    const float4* p0 = (const float4*)(x + (size_t)(b * CIN_ + c0) * HW_);
    const float4* p1 = (const float4*)(x + (size_t)(b * CIN_ + c0 + 1) * HW_);
    uint4* op = (uint4*)(g_xp + ((size_t)b * (CIN_ / 2) + cp) * HW_);
    float s0 = 0.f, s1 = 0.f;
    for (int i = lane; i < 196; i += 32) {
        float4 a = p0[i];
        float4 c = p1[i];
        s0 += (a.x + a.y) + (a.z + a.w);
        s1 += (c.x + c.y) + (c.z + c.w);
        op[i] = make_uint4(pack2h(a.x, c.x), pack2h(a.y, c.y),
                           pack2h(a.z, c.z), pack2h(a.w, c.w));
    }
    #pragma unroll
    for (int o = 16; o; o >>= 1) {
        s0 += __shfl_xor_sync(0xffffffffu, s0, o);
        s1 += __shfl_xor_sync(0xffffffffu, s1, o);
    }
    if (!lane) {
        g_pool[b * CIN_ + c0]     = s0 * (1.f / 784.f);
        g_pool[b * CIN_ + c0 + 1] = s1 * (1.f / 784.f);
    }
}

// ============================================================
// Kernel 0c: convert exp_w to f16x2 with PERMUTED rows
// ============================================================
__global__ void k_cvtw(const float* __restrict__ w) {
    int idx = blockIdx.x * 256 + threadIdx.x;
    int m = idx / 48, kp = idx % 48;
    int ch = (m & ~15) + 2 * (m & 7) + ((m >> 3) & 1);
    const float* wr = w + ch * CIN_ + 2 * kp;
    g_wp[idx] = pack2h(wr[0], wr[1]);
}

// ============================================================
// Kernel 0b: routing MLP + softmax  grid=64 block=32
// ============================================================
__global__ void k_rmlp(const float* __restrict__ w1, const float* __restrict__ b1,
                       const float* __restrict__ w2, const float* __restrict__ b2) {
    int b = blockIdx.x, lane = threadIdx.x;
    __shared__ float pool[CIN_];
    __shared__ float hdn[RHID_];
    __shared__ float lg[NE_];
    for (int i = lane; i < CIN_; i += 32) pool[i] = g_pool[b * CIN_ + i];
    __syncwarp();
    if (lane < RHID_) {
        float a = b1[lane];
        for (int c = 0; c < CIN_; c++) a = fmaf(pool[c], w1[lane * CIN_ + c], a);
        hdn[lane] = fmaxf(a, 0.f);
    }
    __syncwarp();
    if (lane < NE_) {
        float a = b2[lane];
        #pragma unroll
        for (int j = 0; j < RHID_; j++) a = fmaf(hdn[j], w2[lane * RHID_ + j], a);
        lg[lane] = a;
    }
    __syncwarp();
    if (lane == 0) {
        float mx = fmaxf(fmaxf(lg[0], lg[1]), fmaxf(lg[2], lg[3]));
        float e[4], s = 0.f;
        #pragma unroll
        for (int i = 0; i < 4; i++) { e[i] = __expf(lg[i] - mx); s += e[i]; }
        float inv = 1.f / s;
        #pragma unroll
        for (int i = 0; i < 4; i++) g_rw[b * NE_ + i] = e[i] * inv;
    }
}

// ============================================================
// Kernel 1: expand 1x1 GEMM (f16 mma) + BN1 + SiLU -> act1p
// grid=(9,64) block=256 — double-buffered cp.async pipeline over 7 hw-subtiles
// ============================================================
__global__ void k_expand(const float* __restrict__ gg, const float* __restrict__ bb,
                         const float* __restrict__ mm, const float* __restrict__ vv) {
    __shared__ uint32_t xs[2][48][120];
    int b = blockIdx.y, o0 = blockIdx.x * 64;
    int t = threadIdx.x, lane = t & 31, wid = t >> 5;
    int gid = lane >> 2, tig = lane & 3;
    int wm = wid >> 1, wn = wid & 1;

    uint32_t* wsf = &xs[1][0][0];
    for (int i = t; i < 768; i += 256) {
        int m = i / 12, q = i % 12;
        *(uint4*)&wsf[m * 52 + 4 * q] = *(const uint4*)(g_wp + (o0 + m) * 48 + 4 * q);
    }
    __syncthreads();

    int m = wm * 16 + gid;
    uint32_t A[6][4];
    #pragma unroll
    for (int s = 0; s < 6; s++) {
        int kp = s * 8 + tig;
        A[s][0] = wsf[m * 52 + kp];       A[s][1] = wsf[(m + 8) * 52 + kp];
        A[s][2] = wsf[m * 52 + kp + 4];   A[s][3] = wsf[(m + 8) * 52 + kp + 4];
    }
    __syncthreads();

    int ch0 = o0 + wm * 16 + 2 * gid;
    int ch1 = ch0 + 1;
    float inv0 = gg[ch0] * rsqrtf(vv[ch0] + EPSBN), base0 = bb[ch0] - mm[ch0] * inv0;
    float inv1 = gg[ch1] * rsqrtf(vv[ch1] + EPSBN), base1 = bb[ch1] - mm[ch1] * inv1;
    uint32_t* op = g_act1p + ((size_t)b * (HID_ / 2) + (ch0 >> 1)) * HW_;
    const uint32_t* xpb0 = g_xp + (size_t)b * (CIN_ / 2) * HW_;

    int kp0 = t / 28, q0 = t % 28;

    auto fill = [&](int hwt, int buf) {
        const uint32_t* xpb = xpb0 + hwt * 112;
        int kp = kp0, q = q0;
        #pragma unroll
        for (int it = 0; it < 6; it++) {
            if (t + it * 256 < 1344) {
                uint32_t saddr = (uint32_t)__cvta_generic_to_shared(&xs[buf][kp][4 * q]);
                asm volatile("cp.async.cg.shared.global [%0], [%1], 16;\n"
                             :: "r"(saddr), "l"(xpb + kp * HW_ + 4 * q) : "memory");
            }
            q += 4; kp += 9;
            if (q >= 28) { q -= 28; kp++; }
        }
        asm volatile("cp.async.commit_group;\n" ::: "memory");
    };

    fill(0, 0);
    asm volatile("cp.async.wait_group 0;\n" ::: "memory");
    __syncthreads();

    for (int hwt = 0; hwt < 7; hwt++) {
        int cur = hwt & 1;
        if (hwt < 6) fill(hwt + 1, cur ^ 1);

        float acc[7][4] = {};
        #pragma unroll
        for (int s = 0; s < 6; s++) {
            int kp = s * 8 + tig;
            #pragma unroll
            for (int ni = 0; ni < 7; ni++) {
                int n = wn * 56 + ni * 8 + gid;
                mma_f16(acc[ni], A[s][0], A[s][1], A[s][2], A[s][3],
                        xs[cur][kp][n], xs[cur][kp + 4][n]);
            }
        }

        int hw0 = hwt * 112;
        #pragma unroll
        for (int ni = 0; ni < 7; ni++) {
            int n = hw0 + wn * 56 + ni * 8 + tig * 2;
            float a0v = siluf_(fmaf(acc[ni][0], inv0, base0));
            float a1v = siluf_(fmaf(acc[ni][1], inv0, base0));
            float a2v = siluf_(fmaf(acc[ni][2], inv1, base1));
            float a3v = siluf_(fmaf(acc[ni][3], inv1, base1));
            *(uint2*)(op + n) = make_uint2(pack2h(a0v, a2v), pack2h(a1v, a3v));
        }

        if (hwt < 6) {
            asm volatile("cp.async.wait_group 0;\n" ::: "memory");
            __syncthreads();
        }
    }
}

// ============================================================
// Kernel 2: MoE depthwise 5x5 HFMA2 + BN2(h2) + SiLU + SE pool
// grid=(36,64) block=224 — async zfill tile fill overlapped with
// kern-mix; SINGLE barrier
// ============================================================
#define TSTRIDE 1064
__global__ void __launch_bounds__(224, 4) k_dw(
                     const float* __restrict__ dw,
                     const float* __restrict__ gg, const float* __restrict__ bb,
                     const float* __restrict__ mm, const float* __restrict__ vv) {
    int b = blockIdx.y, t = threadIdx.x;
    int cp0 = blockIdx.x * 8;
    __shared__ __half2 tile[8 * TSTRIDE];
    __shared__ __half2 kern[8][25];
    __shared__ float2 part[8][28];

    // 1) async tile fill (zero-fill halo via src-size 0)
    const uint32_t* in = g_act1p + ((size_t)b * (HID_ / 2) + cp0) * HW_;
    for (int idx = t; idx < 8192; idx += 224) {
        int i = idx >> 10, p = idx & 1023;
        int r = p >> 5, c = p & 31;
        int rr = r - 2, cc = c - 2;
        bool ok = (rr >= 0 && rr < 28 && cc >= 0 && cc < 28);
        int ssz = ok ? 4 : 0;
        const uint32_t* src = in + (size_t)i * HW_ + (ok ? rr * 28 + cc : 0);
        uint32_t saddr = (uint32_t)__cvta_generic_to_shared(&tile[i * TSTRIDE + r * 33 + c]);
        asm volatile("cp.async.ca.shared.global [%0], [%1], 4, %2;\n"
                     :: "r"(saddr), "l"(src), "r"(ssz) : "memory");
    }
    asm volatile("cp.async.commit_group;\n" ::: "memory");

    // 2) kern mix overlapped with async fill (reads g_rw direct, no smem dep)
    if (t < 200) {
        int pl = t / 25, kk = t % 25;
        int ch = 2 * (cp0 + pl);
        float s0 = 0.f, s1 = 0.f;
        #pragma unroll
        for (int e = 0; e < NE_; e++) {
            float rwv = g_rw[b * NE_ + e];
            s0 = fmaf(rwv, dw[(e * HID_ + ch)     * 25 + kk], s0);
            s1 = fmaf(rwv, dw[(e * HID_ + ch + 1) * 25 + kk], s1);
        }
        kern[pl][kk] = __floats2half2_rn(s0, s1);
    }

    // 3) single barrier: tile + kern both ready
    asm volatile("cp.async.wait_group 0;\n" ::: "memory");
    __syncthreads();

    int pl = t / 28;
    int patch = t % 28;
    int rg = patch / 7, cg = patch % 7;
    int r0 = rg * 7, cb = cg * 4;
    const __half2* tp = tile + pl * TSTRIDE;

    __half2 kr[25];
    #pragma unroll
    for (int i = 0; i < 25; i++) kr[i] = kern[pl][i];

    __half2 acc[7][4];
    #pragma unroll
    for (int j = 0; j < 7; j++)
        #pragma unroll
        for (int c2 = 0; c2 < 4; c2++) acc[j][c2] = __floats2half2_rn(0.f, 0.f);

    #pragma unroll
    for (int u = 0; u < 11; u++) {
        __half2 w8[8];
        #pragma unroll
        for (int wj = 0; wj < 8; wj++) w8[wj] = tp[(r0 + u) * 33 + cb + wj];
        #pragma unroll
        for (int j = 0; j < 7; j++) {
            if (u >= j && u <= j + 4) {
                int k = u - j;
                #pragma unroll
                for (int c2 = 0; c2 < 4; c2++)
                    #pragma unroll
                    for (int w2 = 0; w2 < 5; w2++)
                        acc[j][c2] = __hfma2(w8[c2 + w2], kr[k * 5 + w2], acc[j][c2]);
            }
        }
    }

    int ch0 = 2 * (cp0 + pl), ch1 = ch0 + 1;
    float inv0 = gg[ch0] * rsqrtf(vv[ch0] + EPSBN), base0 = bb[ch0] - mm[ch0] * inv0;
    float inv1 = gg[ch1] * rsqrtf(vv[ch1] + EPSBN), base1 = bb[ch1] - mm[ch1] * inv1;
    __half2 inv2  = __floats2half2_rn(inv0, inv1);
    __half2 base2 = __floats2half2_rn(base0, base1);
    float ls0 = 0.f, ls1 = 0.f;
    uint32_t* op = g_act2p + ((size_t)b * (HID_ / 2) + cp0 + pl) * HW_;
    #pragma unroll
    for (int j = 0; j < 7; j++) {
        uint32_t pk[4];
        #pragma unroll
        for (int c2 = 0; c2 < 4; c2++) {
            __half2 y = __hfma2(acc[j][c2], inv2, base2);
            float a0 = siluf_(__low2float(y));
            float a1 = siluf_(__high2float(y));
            ls0 += a0; ls1 += a1;
            pk[c2] = pack2h(a0, a1);
        }
        *(uint4*)(op + (r0 + j) * 28 + cb) = make_uint4(pk[0], pk[1], pk[2], pk[3]);
    }
    part[pl][patch] = make_float2(ls0, ls1);
    __syncthreads();
    if (t < 16) {
        int p2 = t >> 1, hi = t & 1;
        float s = 0.f;
        #pragma unroll
        for (int i = 0; i < 28; i++) s += hi ? part[p2][i].y : part[p2][i].x;
        g_s[b * HID_ + 2 * (cp0 + p2) + hi] = s * (1.f / 784.f);
    }
}

// ============================================================
// Kernel 3: SE first layer -> g_zv   grid=64 block=256
// ============================================================
__global__ void k_sez(const float* __restrict__ w1, const float* __restrict__ b1) {
    int b = blockIdx.x, t = threadIdx.x, lane = t & 31, w = t >> 5;
    __shared__ float sv[HID_];
    for (int i = t; i < HID_; i += 256) sv[i] = g_s[b * HID_ + i];
    __syncthreads();
    #pragma unroll
    for (int i = 0; i < 3; i++) {
        int r = w + 8 * i;
        float s = 0.f;
        for (int c = lane; c < HID_; c += 32) s = fmaf(sv[c], w1[r * HID_ + c], s);
        #pragma unroll
        for (int o = 16; o; o >>= 1) s += __shfl_xor_sync(0xffffffffu, s, o);
        if (!lane) g_zv[b * RED_ + r] = siluf_(s + b1[r]);
    }
}

// ============================================================
// Kernel 4: SE second layer + mix pointwise weights + fold scale (f16x2)
// ============================================================
__global__ void k_wpw(const float* __restrict__ pw,
                      const float* __restrict__ w2, const float* __restrict__ b2) {
    int t = threadIdx.x, lane = t & 31, ty = t >> 5;
    int o = blockIdx.y * 8 + ty;
    int cp = blockIdx.x * 32 + lane;
    __shared__ float rws[B_][NE_];
    __shared__ float zvs[B_][RED_];
    __shared__ float scs[B_][64];

    for (int i = t; i < B_ * NE_; i += 256) rws[i >> 2][i & 3] = g_rw[i];
    for (int i = t; i < B_ * RED_; i += 256) zvs[i / RED_][i % RED_] = g_zv[i];
    __syncthreads();
    for (int idx = t; idx < B_ * 64; idx += 256) {
        int bb2 = idx >> 6, j = idx & 63;
        int c = blockIdx.x * 64 + j;
        float a = b2[c];
        #pragma unroll
        for (int r = 0; r < RED_; r++) a = fmaf(zvs[bb2][r], w2[c * RED_ + r], a);
        scs[bb2][j] = sigmoidf_(a);
    }
    __syncthreads();

    float p0[NE_], p1[NE_];
    #pragma unroll
    for (int e = 0; e < NE_; e++) {
        float2 v = *(const float2*)(pw + (size_t)(e * COUT_ + o) * HID_ + 2 * cp);
        p0[e] = v.x; p1[e] = v.y;
    }
    int jl = lane * 2;
    for (int b = 0; b < B_; b++) {
        float w0 = 0.f, w1v = 0.f;
        #pragma unroll
        for (int e = 0; e < NE_; e++) {
            w0  = fmaf(rws[b][e], p0[e], w0);
            w1v = fmaf(rws[b][e], p1[e], w1v);
        }
        g_wpwp[(size_t)(b * COUT_ + o) * (HID_ / 2) + cp] =
            pack2h(w0 * scs[b][jl], w1v * scs[b][jl + 1]);
    }
}

// ============================================================
// Kernel 5: pointwise GEMM (f16 mma) + BN3 + residual
// grid=(9,64) block=256  BM=96 BN=96 BK=64
// double-buffered cp.async over the 9 k-iterations
// ============================================================
__global__ void k_pw(const float* __restrict__ x,
                     const float* __restrict__ gg, const float* __restrict__ bb,
                     const float* __restrict__ mm, const float* __restrict__ vv,
                     float* __restrict__ out) {
    __shared__ uint32_t ws[2][96][36];
    __shared__ uint32_t xs[2][32][104];
    int b = blockIdx.y, n0 = blockIdx.x * 96;
    int t = threadIdx.x, lane = t & 31, wid = t >> 5;
    int gid = lane >> 2, tig = lane & 3;
    int wm = wid >> 2, wn = wid & 3;

    float acc[3][3][4] = {};
    const uint32_t* wp = g_wpwp + (size_t)b * COUT_ * (HID_ / 2);
    const uint32_t* ap = g_act2p + (size_t)b * (HID_ / 2) * HW_;

    auto fill = [&](int it9, int buf) {
        int k0p = it9 * 32;
        #pragma unroll
        for (int r = 0; r < 3; r++) {
            int i = t + r * 256;
            int m = i >> 3, q = i & 7;
            uint32_t saddr = (uint32_t)__cvta_generic_to_shared(&ws[buf][m][4 * q]);
            asm volatile("cp.async.cg.shared.global [%0], [%1], 16;\n"
                         :: "r"(saddr), "l"(wp + m * (HID_ / 2) + k0p + 4 * q) : "memory");
        }
        #pragma unroll
        for (int r = 0; r < 3; r++) {
            int i = t + r * 256;
            int kp = i / 24, q = i % 24;
            int col = n0 + 4 * q;
            int ssz = (col < HW_) ? 16 : 0;
            uint32_t saddr = (uint32_t)__cvta_generic_to_shared(&xs[buf][kp][4 * q]);
            const uint32_t* src = ap + (size_t)(k0p + kp) * HW_ + ((col < HW_) ? col : 0);
            asm volatile("cp.async.cg.shared.global [%0], [%1], 16, %2;\n"
                         :: "r"(saddr), "l"(src), "r"(ssz) : "memory");
        }
        asm volatile("cp.async.commit_group;\n" ::: "memory");
    };

    fill(0, 0);
    asm volatile("cp.async.wait_group 0;\n" ::: "memory");
    __syncthreads();

    for (int it9 = 0; it9 < 9; it9++) {
        int cur = it9 & 1;
        if (it9 < 8) fill(it9 + 1, cur ^ 1);

        #pragma unroll
        for (int s = 0; s < 4; s++) {
            int kp = s * 8 + tig;
            uint32_t A[3][4];
            #pragma unroll
            for (int mi = 0; mi < 3; mi++) {
                int m = wm * 48 + mi * 16 + gid;
                A[mi][0] = ws[cur][m][kp];     A[mi][1] = ws[cur][m + 8][kp];
                A[mi][2] = ws[cur][m][kp + 4]; A[mi][3] = ws[cur][m + 8][kp + 4];
            }
            #pragma unroll
            for (int ni = 0; ni < 3; ni++) {
                int n = wn * 24 + ni * 8 + gid;
                uint32_t b0 = xs[cur][kp][n], b1 = xs[cur][kp + 4][n];
                #pragma unroll
                for (int mi = 0; mi < 3; mi++)
                    mma_f16(acc[mi][ni], A[mi][0], A[mi][1], A[mi][2], A[mi][3], b0, b1);
            }
        }

        if (it9 < 8) {
            asm volatile("cp.async.wait_group 0;\n" ::: "memory");
            __syncthreads();
        }
    }

    #pragma unroll
    for (int mi = 0; mi < 3; mi++) {
        int oA = wm * 48 + mi * 16 + gid;
        int oB = oA + 8;
        float invA = gg[oA] * rsqrtf(vv[oA] + EPSBN), baseA = bb[oA] - mm[oA] * invA;
        float invB = gg[oB] * rsqrtf(vv[oB] + EPSBN), baseB = bb[oB] - mm[oB] * invB;
        #pragma unroll
        for (int ni = 0; ni < 3; ni++) {
            int col = n0 + wn * 24 + ni * 8 + tig * 2;
            if (col < HW_) {
                size_t iA = (size_t)(b * COUT_ + oA) * HW_ + col;
                size_t iB = (size_t)(b * COUT_ + oB) * HW_ + col;
                float2 rA = *(const float2*)(x + iA);
                float2 rB = *(const float2*)(x + iB);
                *(float2*)(out + iA) = make_float2(fmaf(acc[mi][ni][0], invA, baseA) + rA.x,
                                                   fmaf(acc[mi][ni][1], invA, baseA) + rA.y);
                *(float2*)(out + iB) = make_float2(fmaf(acc[mi][ni][2], invB, baseB) + rB.x,
                                                   fmaf(acc[mi][ni][3], invB, baseB) + rB.y);
            }
        }
    }
}

// ============================================================
extern "C" void kernel_launch(void* const* d_in, const int* in_sizes, int n_in,
                              void* d_out, int out_size) {
    const float* x     = (const float*)d_in[0];
    const float* r_w1  = (const float*)d_in[1];
    const float* r_b1  = (const float*)d_in[2];
    const float* r_w2  = (const float*)d_in[3];
    const float* r_b2  = (const float*)d_in[4];
    const float* exp_w = (const float*)d_in[5];
    const float* bn1_g = (const float*)d_in[6];
    const float* bn1_b = (const float*)d_in[7];
    const float* bn1_m = (const float*)d_in[8];
    const float* bn1_v = (const float*)d_in[9];
    const float* dw_w  = (const float*)d_in[10];
    const float* bn2_g = (const float*)d_in[11];
    const float* bn2_b = (const float*)d_in[12];
    const float* bn2_m = (const float*)d_in[13];
    const float* bn2_v = (const float*)d_in[14];
    const float* se_w1 = (const float*)d_in[15];
    const float* se_b1 = (const float*)d_in[16];
    const float* se_w2 = (const float*)d_in[17];
    const float* se_b2 = (const float*)d_in[18];
    const float* pw_w  = (const float*)d_in[19];
    const float* bn3_g = (const float*)d_in[20];
    const float* bn3_b = (const float*)d_in[21];
    const float* bn3_m = (const float*)d_in[22];
    const float* bn3_v = (const float*)d_in[23];
    float* out = (float*)d_out;

    k_pool  <<<dim3(6, B_), 256>>>(x);
    k_cvtw  <<<108, 256>>>(exp_w);
    k_rmlp  <<<B_, 32>>>(r_w1, r_b1, r_w2, r_b2);
    k_expand<<<dim3(9, B_), 256>>>(bn1_g, bn1_b, bn1_m, bn1_v);
    k_dw    <<<dim3(36, B_), 224>>>(dw_w, bn2_g, bn2_b, bn2_m, bn2_v);
    k_sez   <<<B_, 256>>>(se_w1, se_b1);
    k_wpw   <<<dim3(9, 12), 256>>>(pw_w, se_w2, se_b2);
    k_pw    <<<dim3(9, B_), 256>>>(x, bn3_g, bn3_b, bn3_m, bn3_v, out);
}

// round 16
// speedup vs baseline: 1.9860x; 1.0329x over previous
#include <cuda_runtime.h>
#include <cuda_fp16.h>
#include <cstdint>

#define B_    64
#define CIN_  96
#define HW_   784
#define HID_  576
#define NE_   4
#define RED_  24
#define RHID_ 24
#define COUT_ 96
#define EPSBN 1e-3f

// ---- scratch (device globals) ----
__device__ float    g_pool[B_ * CIN_];
__device__ float    g_rw  [B_ * NE_];
__device__ float    g_s   [B_ * HID_];
__device__ float    g_zv  [B_ * RED_];
__device__ __align__(16) uint32_t g_xp  [B_ * (CIN_ / 2) * HW_];     // x as f16x2 k-pairs
__device__ __align__(16) uint32_t g_wp  [HID_ * (CIN_ / 2)];         // exp_w f16x2, rows PERMUTED
__device__ __align__(16) uint32_t g_wpwp [B_ * COUT_ * (HID_ / 2)];  // f16x2 pairs along c
__device__ __align__(16) uint32_t g_act1p[B_ * (HID_ / 2) * HW_];    // f16x2 (ch even, ch odd)/pixel
__device__ __align__(16) uint32_t g_act2p[B_ * (HID_ / 2) * HW_];    // f16x2 (ch even, ch odd)/pixel

// silu(v) = h + h*tanh(h), h = v/2 — ONE scalar MUFU
__device__ __forceinline__ float siluf_(float v) {
    float h = 0.5f * v;
    float t; asm("tanh.approx.f32 %0, %1;" : "=f"(t) : "f"(h));
    return fmaf(h, t, h);
}
// sigmoid(v) = 0.5 + 0.5*tanh(v/2) — ONE scalar MUFU
__device__ __forceinline__ float sigmoidf_(float v) {
    float t; asm("tanh.approx.f32 %0, %1;" : "=f"(t) : "f"(0.5f * v));
    return fmaf(0.5f, t, 0.5f);
}

__device__ __forceinline__ uint32_t pack2h(float lo, float hi) {
    uint32_t r; asm("cvt.rn.f16x2.f32 %0, %1, %2;" : "=r"(r) : "f"(hi), "f"(lo)); return r;
}

__device__ __forceinline__ void mma_f16(float* d,
        uint32_t a0, uint32_t a1, uint32_t a2, uint32_t a3,
        uint32_t b0, uint32_t b1) {
    asm volatile(
        "mma.sync.aligned.m16n8k16.row.col.f32.f16.f16.f32 "
        "{%0,%1,%2,%3}, {%4,%5,%6,%7}, {%8,%9}, {%0,%1,%2,%3};\n"
        : "+f"(d[0]), "+f"(d[1]), "+f"(d[2]), "+f"(d[3])
        : "r"(a0), "r"(a1), "r"(a2), "r"(a3), "r"(b0), "r"(b1));
}

// ============================================================
// Kernel 0a: global average pool + pack x + (strip x==6) cvt exp_w
// grid=(7,64) block=256
// ============================================================
__global__ void k_pool(const float* __restrict__ x, const float* __restrict__ w) {
    int b = blockIdx.y, t = threadIdx.x, lane = t & 31, wrp = t >> 5;
    if (blockIdx.x == 6) {
        // weight conversion strip: 27648 words over 64 blocks = 432 each
        int base = b * 432;
        for (int i = t; i < 432; i += 256) {
            int idx = base + i;
            int m = idx / 48, kp = idx % 48;
            int ch = (m & ~15) + 2 * (m & 7) + ((m >> 3) & 1);
            const float* wr = w + ch * CIN_ + 2 * kp;
            g_wp[idx] = pack2h(wr[0], wr[1]);
        }
        return;
    }
    int c0 = blockIdx.x * 16 + wrp * 2;
    int cp = c0 >> 1;
    const float4* p0 = (const float4*)(x + (size_t)(b * CIN_ + c0) * HW_);
    const float4* p1 = (const float4*)(x + (size_t)(b * CIN_ + c0 + 1) * HW_);
    uint4* op = (uint4*)(g_xp + ((size_t)b * (CIN_ / 2) + cp) * HW_);
    float s0 = 0.f, s1 = 0.f;
    for (int i = lane; i < 196; i += 32) {
        float4 a = p0[i];
        float4 c = p1[i];
        s0 += (a.x + a.y) + (a.z + a.w);
        s1 += (c.x + c.y) + (c.z + c.w);
        op[i] = make_uint4(pack2h(a.x, c.x), pack2h(a.y, c.y),
                           pack2h(a.z, c.z), pack2h(a.w, c.w));
    }
    #pragma unroll
    for (int o = 16; o; o >>= 1) {
        s0 += __shfl_xor_sync(0xffffffffu, s0, o);
        s1 += __shfl_xor_sync(0xffffffffu, s1, o);
    }
    if (!lane) {
        g_pool[b * CIN_ + c0]     = s0 * (1.f / 784.f);
        g_pool[b * CIN_ + c0 + 1] = s1 * (1.f / 784.f);
    }
}

// ============================================================
// Kernel 0b: routing MLP + softmax  grid=64 block=32
// ============================================================
__global__ void k_rmlp(const float* __restrict__ w1, const float* __restrict__ b1,
                       const float* __restrict__ w2, const float* __restrict__ b2) {
    int b = blockIdx.x, lane = threadIdx.x;
    __shared__ float pool[CIN_];
    __shared__ float hdn[RHID_];
    __shared__ float lg[NE_];
    for (int i = lane; i < CIN_; i += 32) pool[i] = g_pool[b * CIN_ + i];
    __syncwarp();
    if (lane < RHID_) {
        float a = b1[lane];
        for (int c = 0; c < CIN_; c++) a = fmaf(pool[c], w1[lane * CIN_ + c], a);
        hdn[lane] = fmaxf(a, 0.f);
    }
    __syncwarp();
    if (lane < NE_) {
        float a = b2[lane];
        #pragma unroll
        for (int j = 0; j < RHID_; j++) a = fmaf(hdn[j], w2[lane * RHID_ + j], a);
        lg[lane] = a;
    }
    __syncwarp();
    if (lane == 0) {
        float mx = fmaxf(fmaxf(lg[0], lg[1]), fmaxf(lg[2], lg[3]));
        float e[4], s = 0.f;
        #pragma unroll
        for (int i = 0; i < 4; i++) { e[i] = __expf(lg[i] - mx); s += e[i]; }
        float inv = 1.f / s;
        #pragma unroll
        for (int i = 0; i < 4; i++) g_rw[b * NE_ + i] = e[i] * inv;
    }
}

// ============================================================
// Kernel 1: expand 1x1 GEMM (f16 mma) + BN1 + SiLU -> act1p
// grid=(9,64) block=256 — double-buffered cp.async; 4 blocks/SM forced
// ============================================================
__global__ void __launch_bounds__(256, 4) k_expand(
                         const float* __restrict__ gg, const float* __restrict__ bb,
                         const float* __restrict__ mm, const float* __restrict__ vv) {
    __shared__ uint32_t xs[2][48][120];
    int b = blockIdx.y, o0 = blockIdx.x * 64;
    int t = threadIdx.x, lane = t & 31, wid = t >> 5;
    int gid = lane >> 2, tig = lane & 3;
    int wm = wid >> 1, wn = wid & 1;

    uint32_t* wsf = &xs[1][0][0];
    for (int i = t; i < 768; i += 256) {
        int m = i / 12, q = i % 12;
        *(uint4*)&wsf[m * 52 + 4 * q] = *(const uint4*)(g_wp + (o0 + m) * 48 + 4 * q);
    }
    __syncthreads();

    int m = wm * 16 + gid;
    uint32_t A[6][4];
    #pragma unroll
    for (int s = 0; s < 6; s++) {
        int kp = s * 8 + tig;
        A[s][0] = wsf[m * 52 + kp];       A[s][1] = wsf[(m + 8) * 52 + kp];
        A[s][2] = wsf[m * 52 + kp + 4];   A[s][3] = wsf[(m + 8) * 52 + kp + 4];
    }
    __syncthreads();

    int ch0 = o0 + wm * 16 + 2 * gid;
    int ch1 = ch0 + 1;
    float inv0 = gg[ch0] * rsqrtf(vv[ch0] + EPSBN), base0 = bb[ch0] - mm[ch0] * inv0;
    float inv1 = gg[ch1] * rsqrtf(vv[ch1] + EPSBN), base1 = bb[ch1] - mm[ch1] * inv1;
    uint32_t* op = g_act1p + ((size_t)b * (HID_ / 2) + (ch0 >> 1)) * HW_;
    const uint32_t* xpb0 = g_xp + (size_t)b * (CIN_ / 2) * HW_;

    int kp0 = t / 28, q0 = t % 28;

    auto fill = [&](int hwt, int buf) {
        const uint32_t* xpb = xpb0 + hwt * 112;
        int kp = kp0, q = q0;
        #pragma unroll
        for (int it = 0; it < 6; it++) {
            if (t + it * 256 < 1344) {
                uint32_t saddr = (uint32_t)__cvta_generic_to_shared(&xs[buf][kp][4 * q]);
                asm volatile("cp.async.cg.shared.global [%0], [%1], 16;\n"
                             :: "r"(saddr), "l"(xpb + kp * HW_ + 4 * q) : "memory");
            }
            q += 4; kp += 9;
            if (q >= 28) { q -= 28; kp++; }
        }
        asm volatile("cp.async.commit_group;\n" ::: "memory");
    };

    fill(0, 0);
    asm volatile("cp.async.wait_group 0;\n" ::: "memory");
    __syncthreads();

    for (int hwt = 0; hwt < 7; hwt++) {
        int cur = hwt & 1;
        if (hwt < 6) fill(hwt + 1, cur ^ 1);

        float acc[7][4] = {};
        #pragma unroll
        for (int s = 0; s < 6; s++) {
            int kp = s * 8 + tig;
            #pragma unroll
            for (int ni = 0; ni < 7; ni++) {
                int n = wn * 56 + ni * 8 + gid;
                mma_f16(acc[ni], A[s][0], A[s][1], A[s][2], A[s][3],
                        xs[cur][kp][n], xs[cur][kp + 4][n]);
            }
        }

        int hw0 = hwt * 112;
        #pragma unroll
        for (int ni = 0; ni < 7; ni++) {
            int n = hw0 + wn * 56 + ni * 8 + tig * 2;
            float a0v = siluf_(fmaf(acc[ni][0], inv0, base0));
            float a1v = siluf_(fmaf(acc[ni][1], inv0, base0));
            float a2v = siluf_(fmaf(acc[ni][2], inv1, base1));
            float a3v = siluf_(fmaf(acc[ni][3], inv1, base1));
            *(uint2*)(op + n) = make_uint2(pack2h(a0v, a2v), pack2h(a1v, a3v));
        }

        if (hwt < 6) {
            asm volatile("cp.async.wait_group 0;\n" ::: "memory");
            __syncthreads();
        }
    }
}

// ============================================================
// Kernel 2: MoE depthwise 5x5 HFMA2 + BN2(h2) + SiLU + SE pool
// grid=(36,64) block=224 — async zfill + kern-mix overlap, single barrier
// ============================================================
#define TSTRIDE 1064
__global__ void __launch_bounds__(224, 4) k_dw(
                     const float* __restrict__ dw,
                     const float* __restrict__ gg, const float* __restrict__ bb,
                     const float* __restrict__ mm, const float* __restrict__ vv) {
    int b = blockIdx.y, t = threadIdx.x;
    int cp0 = blockIdx.x * 8;
    __shared__ __half2 tile[8 * TSTRIDE];
    __shared__ __half2 kern[8][25];
    __shared__ float2 part[8][28];

    const uint32_t* in = g_act1p + ((size_t)b * (HID_ / 2) + cp0) * HW_;
    for (int idx = t; idx < 8192; idx += 224) {
        int i = idx >> 10, p = idx & 1023;
        int r = p >> 5, c = p & 31;
        int rr = r - 2, cc = c - 2;
        bool ok = (rr >= 0 && rr < 28 && cc >= 0 && cc < 28);
        int ssz = ok ? 4 : 0;
        const uint32_t* src = in + (size_t)i * HW_ + (ok ? rr * 28 + cc : 0);
        uint32_t saddr = (uint32_t)__cvta_generic_to_shared(&tile[i * TSTRIDE + r * 33 + c]);
        asm volatile("cp.async.ca.shared.global [%0], [%1], 4, %2;\n"
                     :: "r"(saddr), "l"(src), "r"(ssz) : "memory");
    }
    asm volatile("cp.async.commit_group;\n" ::: "memory");

    if (t < 200) {
        int pl = t / 25, kk = t % 25;
        int ch = 2 * (cp0 + pl);
        float s0 = 0.f, s1 = 0.f;
        #pragma unroll
        for (int e = 0; e < NE_; e++) {
            float rwv = g_rw[b * NE_ + e];
            s0 = fmaf(rwv, dw[(e * HID_ + ch)     * 25 + kk], s0);
            s1 = fmaf(rwv, dw[(e * HID_ + ch + 1) * 25 + kk], s1);
        }
        kern[pl][kk] = __floats2half2_rn(s0, s1);
    }

    asm volatile("cp.async.wait_group 0;\n" ::: "memory");
    __syncthreads();

    int pl = t / 28;
    int patch = t % 28;
    int rg = patch / 7, cg = patch % 7;
    int r0 = rg * 7, cb = cg * 4;
    const __half2* tp = tile + pl * TSTRIDE;

    __half2 kr[25];
    #pragma unroll
    for (int i = 0; i < 25; i++) kr[i] = kern[pl][i];

    __half2 acc[7][4];
    #pragma unroll
    for (int j = 0; j < 7; j++)
        #pragma unroll
        for (int c2 = 0; c2 < 4; c2++) acc[j][c2] = __floats2half2_rn(0.f, 0.f);

    #pragma unroll
    for (int u = 0; u < 11; u++) {
        __half2 w8[8];
        #pragma unroll
        for (int wj = 0; wj < 8; wj++) w8[wj] = tp[(r0 + u) * 33 + cb + wj];
        #pragma unroll
        for (int j = 0; j < 7; j++) {
            if (u >= j && u <= j + 4) {
                int k = u - j;
                #pragma unroll
                for (int c2 = 0; c2 < 4; c2++)
                    #pragma unroll
                    for (int w2 = 0; w2 < 5; w2++)
                        acc[j][c2] = __hfma2(w8[c2 + w2], kr[k * 5 + w2], acc[j][c2]);
            }
        }
    }

    int ch0 = 2 * (cp0 + pl), ch1 = ch0 + 1;
    float inv0 = gg[ch0] * rsqrtf(vv[ch0] + EPSBN), base0 = bb[ch0] - mm[ch0] * inv0;
    float inv1 = gg[ch1] * rsqrtf(vv[ch1] + EPSBN), base1 = bb[ch1] - mm[ch1] * inv1;
    __half2 inv2  = __floats2half2_rn(inv0, inv1);
    __half2 base2 = __floats2half2_rn(base0, base1);
    float ls0 = 0.f, ls1 = 0.f;
    uint32_t* op = g_act2p + ((size_t)b * (HID_ / 2) + cp0 + pl) * HW_;
    #pragma unroll
    for (int j = 0; j < 7; j++) {
        uint32_t pk[4];
        #pragma unroll
        for (int c2 = 0; c2 < 4; c2++) {
            __half2 y = __hfma2(acc[j][c2], inv2, base2);
            float a0 = siluf_(__low2float(y));
            float a1 = siluf_(__high2float(y));
            ls0 += a0; ls1 += a1;
            pk[c2] = pack2h(a0, a1);
        }
        *(uint4*)(op + (r0 + j) * 28 + cb) = make_uint4(pk[0], pk[1], pk[2], pk[3]);
    }
    part[pl][patch] = make_float2(ls0, ls1);
    __syncthreads();
    if (t < 16) {
        int p2 = t >> 1, hi = t & 1;
        float s = 0.f;
        #pragma unroll
        for (int i = 0; i < 28; i++) s += hi ? part[p2][i].y : part[p2][i].x;
        g_s[b * HID_ + 2 * (cp0 + p2) + hi] = s * (1.f / 784.f);
    }
}

// ============================================================
// Kernel 3: SE first layer -> g_zv   grid=64 block=256
// ============================================================
__global__ void k_sez(const float* __restrict__ w1, const float* __restrict__ b1) {
    int b = blockIdx.x, t = threadIdx.x, lane = t & 31, w = t >> 5;
    __shared__ float sv[HID_];
    for (int i = t; i < HID_; i += 256) sv[i] = g_s[b * HID_ + i];
    __syncthreads();
    #pragma unroll
    for (int i = 0; i < 3; i++) {
        int r = w + 8 * i;
        float s = 0.f;
        for (int c = lane; c < HID_; c += 32) s = fmaf(sv[c], w1[r * HID_ + c], s);
        #pragma unroll
        for (int o = 16; o; o >>= 1) s += __shfl_xor_sync(0xffffffffu, s, o);
        if (!lane) g_zv[b * RED_ + r] = siluf_(s + b1[r]);
    }
}

// ============================================================
// Kernel 4: SE second layer + mix pointwise weights + fold scale (f16x2)
// ============================================================
__global__ void k_wpw(const float* __restrict__ pw,
                      const float* __restrict__ w2, const float* __restrict__ b2) {
    int t = threadIdx.x, lane = t & 31, ty = t >> 5;
    int o = blockIdx.y * 8 + ty;
    int cp = blockIdx.x * 32 + lane;
    __shared__ float rws[B_][NE_];
    __shared__ float zvs[B_][RED_];
    __shared__ float scs[B_][64];

    for (int i = t; i < B_ * NE_; i += 256) rws[i >> 2][i & 3] = g_rw[i];
    for (int i = t; i < B_ * RED_; i += 256) zvs[i / RED_][i % RED_] = g_zv[i];
    __syncthreads();
    for (int idx = t; idx < B_ * 64; idx += 256) {
        int bb2 = idx >> 6, j = idx & 63;
        int c = blockIdx.x * 64 + j;
        float a = b2[c];
        #pragma unroll
        for (int r = 0; r < RED_; r++) a = fmaf(zvs[bb2][r], w2[c * RED_ + r], a);
        scs[bb2][j] = sigmoidf_(a);
    }
    __syncthreads();

    float p0[NE_], p1[NE_];
    #pragma unroll
    for (int e = 0; e < NE_; e++) {
        float2 v = *(const float2*)(pw + (size_t)(e * COUT_ + o) * HID_ + 2 * cp);
        p0[e] = v.x; p1[e] = v.y;
    }
    int jl = lane * 2;
    for (int b = 0; b < B_; b++) {
        float w0 = 0.f, w1v = 0.f;
        #pragma unroll
        for (int e = 0; e < NE_; e++) {
            w0  = fmaf(rws[b][e], p0[e], w0);
            w1v = fmaf(rws[b][e], p1[e], w1v);
        }
        g_wpwp[(size_t)(b * COUT_ + o) * (HID_ / 2) + cp] =
            pack2h(w0 * scs[b][jl], w1v * scs[b][jl + 1]);
    }
}

// ============================================================
// Kernel 5: pointwise GEMM (f16 mma) + BN3 + residual
// grid=(9,64) block=256  BM=96 BN=96 BK=64; db cp.async; 4 blocks/SM forced
// ============================================================
__global__ void __launch_bounds__(256, 4) k_pw(
                     const float* __restrict__ x,
                     const float* __restrict__ gg, const float* __restrict__ bb,
                     const float* __restrict__ mm, const float* __restrict__ vv,
                     float* __restrict__ out) {
    __shared__ uint32_t ws[2][96][36];
    __shared__ uint32_t xs[2][32][104];
    int b = blockIdx.y, n0 = blockIdx.x * 96;
    int t = threadIdx.x, lane = t & 31, wid = t >> 5;
    int gid = lane >> 2, tig = lane & 3;
    int wm = wid >> 2, wn = wid & 3;

    float acc[3][3][4] = {};
    const uint32_t* wp = g_wpwp + (size_t)b * COUT_ * (HID_ / 2);
    const uint32_t* ap = g_act2p + (size_t)b * (HID_ / 2) * HW_;

    auto fill = [&](int it9, int buf) {
        int k0p = it9 * 32;
        #pragma unroll
        for (int r = 0; r < 3; r++) {
            int i = t + r * 256;
            int m = i >> 3, q = i & 7;
            uint32_t saddr = (uint32_t)__cvta_generic_to_shared(&ws[buf][m][4 * q]);
            asm volatile("cp.async.cg.shared.global [%0], [%1], 16;\n"
                         :: "r"(saddr), "l"(wp + m * (HID_ / 2) + k0p + 4 * q) : "memory");
        }
        #pragma unroll
        for (int r = 0; r < 3; r++) {
            int i = t + r * 256;
            int kp = i / 24, q = i % 24;
            int col = n0 + 4 * q;
            int ssz = (col < HW_) ? 16 : 0;
            uint32_t saddr = (uint32_t)__cvta_generic_to_shared(&xs[buf][kp][4 * q]);
            const uint32_t* src = ap + (size_t)(k0p + kp) * HW_ + ((col < HW_) ? col : 0);
            asm volatile("cp.async.cg.shared.global [%0], [%1], 16, %2;\n"
                         :: "r"(saddr), "l"(src), "r"(ssz) : "memory");
        }
        asm volatile("cp.async.commit_group;\n" ::: "memory");
    };

    fill(0, 0);
    asm volatile("cp.async.wait_group 0;\n" ::: "memory");
    __syncthreads();

    for (int it9 = 0; it9 < 9; it9++) {
        int cur = it9 & 1;
        if (it9 < 8) fill(it9 + 1, cur ^ 1);

        #pragma unroll
        for (int s = 0; s < 4; s++) {
            int kp = s * 8 + tig;
            uint32_t A[3][4];
            #pragma unroll
            for (int mi = 0; mi < 3; mi++) {
                int m = wm * 48 + mi * 16 + gid;
                A[mi][0] = ws[cur][m][kp];     A[mi][1] = ws[cur][m + 8][kp];
                A[mi][2] = ws[cur][m][kp + 4]; A[mi][3] = ws[cur][m + 8][kp + 4];
            }
            #pragma unroll
            for (int ni = 0; ni < 3; ni++) {
                int n = wn * 24 + ni * 8 + gid;
                uint32_t b0 = xs[cur][kp][n], b1 = xs[cur][kp + 4][n];
                #pragma unroll
                for (int mi = 0; mi < 3; mi++)
                    mma_f16(acc[mi][ni], A[mi][0], A[mi][1], A[mi][2], A[mi][3], b0, b1);
            }
        }

        if (it9 < 8) {
            asm volatile("cp.async.wait_group 0;\n" ::: "memory");
            __syncthreads();
        }
    }

    #pragma unroll
    for (int mi = 0; mi < 3; mi++) {
        int oA = wm * 48 + mi * 16 + gid;
        int oB = oA + 8;
        float invA = gg[oA] * rsqrtf(vv[oA] + EPSBN), baseA = bb[oA] - mm[oA] * invA;
        float invB = gg[oB] * rsqrtf(vv[oB] + EPSBN), baseB = bb[oB] - mm[oB] * invB;
        #pragma unroll
        for (int ni = 0; ni < 3; ni++) {
            int col = n0 + wn * 24 + ni * 8 + tig * 2;
            if (col < HW_) {
                size_t iA = (size_t)(b * COUT_ + oA) * HW_ + col;
                size_t iB = (size_t)(b * COUT_ + oB) * HW_ + col;
                float2 rA = *(const float2*)(x + iA);
                float2 rB = *(const float2*)(x + iB);
                *(float2*)(out + iA) = make_float2(fmaf(acc[mi][ni][0], invA, baseA) + rA.x,
                                                   fmaf(acc[mi][ni][1], invA, baseA) + rA.y);
                *(float2*)(out + iB) = make_float2(fmaf(acc[mi][ni][2], invB, baseB) + rB.x,
                                                   fmaf(acc[mi][ni][3], invB, baseB) + rB.y);
            }
        }
    }
}

// ============================================================
extern "C" void kernel_launch(void* const* d_in, const int* in_sizes, int n_in,
                              void* d_out, int out_size) {
    const float* x     = (const float*)d_in[0];
    const float* r_w1  = (const float*)d_in[1];
    const float* r_b1  = (const float*)d_in[2];
    const float* r_w2  = (const float*)d_in[3];
    const float* r_b2  = (const float*)d_in[4];
    const float* exp_w = (const float*)d_in[5];
    const float* bn1_g = (const float*)d_in[6];
    const float* bn1_b = (const float*)d_in[7];
    const float* bn1_m = (const float*)d_in[8];
    const float* bn1_v = (const float*)d_in[9];
    const float* dw_w  = (const float*)d_in[10];
    const float* bn2_g = (const float*)d_in[11];
    const float* bn2_b = (const float*)d_in[12];
    const float* bn2_m = (const float*)d_in[13];
    const float* bn2_v = (const float*)d_in[14];
    const float* se_w1 = (const float*)d_in[15];
    const float* se_b1 = (const float*)d_in[16];
    const float* se_w2 = (const float*)d_in[17];
    const float* se_b2 = (const float*)d_in[18];
    const float* pw_w  = (const float*)d_in[19];
    const float* bn3_g = (const float*)d_in[20];
    const float* bn3_b = (const float*)d_in[21];
    const float* bn3_m = (const float*)d_in[22];
    const float* bn3_v = (const float*)d_in[23];
    float* out = (float*)d_out;

    k_pool  <<<dim3(7, B_), 256>>>(x, exp_w);
    k_rmlp  <<<B_, 32>>>(r_w1, r_b1, r_w2, r_b2);
    k_expand<<<dim3(9, B_), 256>>>(bn1_g, bn1_b, bn1_m, bn1_v);
    k_dw    <<<dim3(36, B_), 224>>>(dw_w, bn2_g, bn2_b, bn2_m, bn2_v);
    k_sez   <<<B_, 256>>>(se_w1, se_b1);
    k_wpw   <<<dim3(9, 12), 256>>>(pw_w, se_w2, se_b2);
    k_pw    <<<dim3(9, B_), 256>>>(x, bn3_g, bn3_b, bn3_m, bn3_v, out);
}